// round 14
// baseline (speedup 1.0000x reference)
#include <cuda_runtime.h>
#include <math.h>
#include <stdint.h>

#define B_   2
#define S_   2048
#define LC_  1024
#define F_   1024
#define DC_  768
#define H_   16
#define HD_  64

// ---------------- scratch (no allocation allowed; zero-initialized) ----------------
__device__ __align__(16) float g_Qr[(size_t)B_ * S_ * F_];
__device__ __align__(16) float g_Qi[(size_t)B_ * S_ * F_];
__device__ __align__(16) float g_Kr[(size_t)B_ * LC_ * F_];
__device__ __align__(16) float g_Ki[(size_t)B_ * LC_ * F_];
__device__ __align__(16) float g_Vr[(size_t)B_ * LC_ * F_];
__device__ __align__(16) float g_Vi[(size_t)B_ * LC_ * F_];
__device__ __align__(16) float g_Or[(size_t)B_ * S_ * F_];
__device__ __align__(16) float g_Oi[(size_t)B_ * S_ * F_];
__device__ __align__(16) float g_S [(size_t)B_ * H_ * S_ * LC_];   // scores -> probs

// ---------------- tf32 mma helpers ----------------
__device__ __forceinline__ uint32_t f2tf32(float x) {
    uint32_t r;
    asm("cvt.rna.tf32.f32 %0, %1;" : "=r"(r) : "f"(x));
    return r;
}

__device__ __forceinline__ void mma_tf32(float c[4], const uint32_t a[4], const uint32_t b[2]) {
    asm volatile(
        "mma.sync.aligned.m16n8k8.row.col.f32.tf32.tf32.f32 "
        "{%0,%1,%2,%3}, {%4,%5,%6,%7}, {%8,%9}, {%0,%1,%2,%3};"
        : "+f"(c[0]), "+f"(c[1]), "+f"(c[2]), "+f"(c[3])
        : "r"(a[0]), "r"(a[1]), "r"(a[2]), "r"(a[3]), "r"(b[0]), "r"(b[1]));
}

// Fragment-packed layouts (64x16 A tile, 16x128 B tile, m16n8k8):
//   A slot: group gA = warpM*4 + ma*2 + kcg (8 groups) x lane -> 4 floats (uint4)
//     regs = {A[mb][kc+qk], A[mb+8][kc+qk], A[mb][kc+qk+4], A[mb+8][kc+qk+4]},
//     mb = warpM*32 + ma*16 + qrow, kc = kcg*8
//   B slot: group gB = warpN*8 + na*2 + kcg (32 groups) x lane -> 2 floats (uint2)
//     regs = {B[kc+qk][nb], B[kc+qk+4][nb]}, nb = warpN*32 + na*8 + qrow
// Producer A: thread t -> (gA = t>>5, lane = t&31), one uint4 store.
// Producer B: thread t -> pg = t>>5 encodes (na = pg>>1, kcg = pg&1); loop warpN
//   (gB = warpN*8 + pg), one uint2 store each.
// All LDS/STS phases are 128B-contiguous -> bank-conflict-free.

// ---------------- complex GEMM via tf32 tensor cores (packed fragments) ----------------
template <int MODE>
__global__ void __launch_bounds__(256, 2) cgemm_kernel(
    int M, int K, int N,
    const float* __restrict__ Ap_r, const float* __restrict__ Ap_i,
    const float* __restrict__ Br, const float* __restrict__ Bi,
    const float* __restrict__ bbr, const float* __restrict__ bbi,
    float* __restrict__ outF, int omode)
{
    const float* __restrict__ Ar = (MODE == 3) ? g_Or : Ap_r;
    const float* __restrict__ Ai = (MODE == 3) ? g_Oi : Ap_i;

    __shared__ uint4 sAr4[256], sAi4[256];
    __shared__ uint2 sBr2[1024], sBi2[1024], sBni2[1024];

    const int tid = threadIdx.x;
    const int warp = tid >> 5, lane = tid & 31;
    const int qrow = lane >> 2, qk = lane & 3;
    const int warpM = warp >> 2;
    const int warpN = warp & 3;
    const int m0 = blockIdx.y << 6;
    const int n0 = blockIdx.x << 7;

    float accr[2][4][4] = {};
    float acci[2][4][4] = {};

    // producer mapping
    const int pg = tid >> 5, pl = tid & 31;
    const int pqrow = pl >> 2, pqk = pl & 3;
    const int pArow = (pg >> 2) * 32 + ((pg >> 1) & 1) * 16 + pqrow;
    const int pAk   = (pg & 1) * 8 + pqk;
    const int pBk   = pAk;
    const int pBcol = ((pg >> 1) & 3) * 8 + pqrow;

    float4 par, pai;
    float2 pbr[4], pbi[4];

    auto load_g = [&](int k0) {
        size_t ga = (size_t)(m0 + pArow) * K + (k0 + pAk);
        size_t ga8 = ga + (size_t)8 * K;
        par.x = Ar[ga];  par.y = Ar[ga8];  par.z = Ar[ga + 4];  par.w = Ar[ga8 + 4];
        pai.x = Ai[ga];  pai.y = Ai[ga8];  pai.z = Ai[ga + 4];  pai.w = Ai[ga8 + 4];
#pragma unroll
        for (int w = 0; w < 4; w++) {
            size_t gb = (size_t)(k0 + pBk) * N + (n0 + w * 32 + pBcol);
            pbr[w].x = Br[gb];  pbr[w].y = Br[gb + (size_t)4 * N];
            pbi[w].x = Bi[gb];  pbi[w].y = Bi[gb + (size_t)4 * N];
        }
    };
    auto store_s = [&]() {
        sAr4[pg * 32 + pl] = make_uint4(f2tf32(par.x), f2tf32(par.y), f2tf32(par.z), f2tf32(par.w));
        sAi4[pg * 32 + pl] = make_uint4(f2tf32(pai.x), f2tf32(pai.y), f2tf32(pai.z), f2tf32(pai.w));
#pragma unroll
        for (int w = 0; w < 4; w++) {
            int gb = w * 8 + pg;
            sBr2[gb * 32 + pl]  = make_uint2(f2tf32(pbr[w].x), f2tf32(pbr[w].y));
            sBi2[gb * 32 + pl]  = make_uint2(f2tf32(pbi[w].x), f2tf32(pbi[w].y));
            sBni2[gb * 32 + pl] = make_uint2(f2tf32(-pbi[w].x), f2tf32(-pbi[w].y));
        }
    };

    load_g(0);
    store_s();
    __syncthreads();

    for (int k0 = 0; k0 < K; k0 += 16) {
        const bool more = (k0 + 16 < K);
        if (more) load_g(k0 + 16);

#pragma unroll
        for (int kcg = 0; kcg < 2; kcg++) {
            uint4 ar[2], ai[2];
#pragma unroll
            for (int ma = 0; ma < 2; ma++) {
                ar[ma] = sAr4[(warpM * 4 + ma * 2 + kcg) * 32 + lane];
                ai[ma] = sAi4[(warpM * 4 + ma * 2 + kcg) * 32 + lane];
            }
#pragma unroll
            for (int na = 0; na < 4; na++) {
                int gb = (warpN * 8 + na * 2 + kcg) * 32 + lane;
                uint2 br2  = sBr2[gb];
                uint2 bi2  = sBi2[gb];
                uint2 bni2 = sBni2[gb];
#pragma unroll
                for (int ma = 0; ma < 2; ma++) {
                    mma_tf32(accr[ma][na], (const uint32_t*)&ar[ma], (const uint32_t*)&br2);
                    mma_tf32(accr[ma][na], (const uint32_t*)&ai[ma], (const uint32_t*)&bni2);
                    mma_tf32(acci[ma][na], (const uint32_t*)&ar[ma], (const uint32_t*)&bi2);
                    mma_tf32(acci[ma][na], (const uint32_t*)&ai[ma], (const uint32_t*)&br2);
                }
            }
        }

        if (more) {
            __syncthreads();
            store_s();
            __syncthreads();
        }
    }

#pragma unroll
    for (int ma = 0; ma < 2; ma++) {
#pragma unroll
        for (int na = 0; na < 4; na++) {
#pragma unroll
            for (int c = 0; c < 4; c++) {
                int row = m0 + warpM * 32 + ma * 16 + qrow + ((c >= 2) ? 8 : 0);
                int col = n0 + warpN * 32 + na * 8 + qk * 2 + (c & 1);
                float vr = accr[ma][na][c] + (bbr ? bbr[col] : 0.0f);
                float vi = acci[ma][na][c] + (bbi ? bbi[col] : 0.0f);
                size_t idx = (size_t)row * N + col;
                if (MODE == 0)      { g_Qr[idx] = vr; g_Qi[idx] = vi; }
                else if (MODE == 1) { g_Kr[idx] = vr; g_Ki[idx] = vi; }
                else if (MODE == 2) { g_Vr[idx] = vr; g_Vi[idx] = vi; }
                else {
                    if (omode == 2) { outF[2 * idx] = vr; outF[2 * idx + 1] = vi; }
                    else            { outF[idx] = vr; }
                }
            }
        }
    }
}

// ---------------- QK batched GEMM (packed): S = (Qr.Kr^T + Qi.Ki^T) * scale ----------------
__global__ void __launch_bounds__(256, 2) qk_kernel()
{
    __shared__ uint4 sAh4[256], sAl4[256];
    __shared__ uint2 sB2[1024];

    const int tid = threadIdx.x;
    const int warp = tid >> 5, lane = tid & 31;
    const int qrow = lane >> 2, qk = lane & 3;
    const int warpM = warp >> 2;
    const int warpN = warp & 3;
    const int m0 = blockIdx.y << 6;
    const int n0 = blockIdx.x << 7;
    const int b  = blockIdx.z >> 4;
    const int h  = blockIdx.z & 15;

    float acc[2][4][4] = {};

    const int pg = tid >> 5, pl = tid & 31;
    const int pqrow = pl >> 2, pqk = pl & 3;
    const int pArow = (pg >> 2) * 32 + ((pg >> 1) & 1) * 16 + pqrow;
    const int pAk   = (pg & 1) * 8 + pqk;
    const int pBcol = ((pg >> 1) & 3) * 8 + pqrow;

    float4 pa;
    float2 pb[4];

    auto load_g = [&](int k0) {
        const float* __restrict__ Qsrc = (k0 < 64) ? g_Qr : g_Qi;
        const float* __restrict__ Ksrc = (k0 < 64) ? g_Kr : g_Ki;
        const int dbase = (k0 & 63);
        size_t ga = ((size_t)(b * S_ + m0 + pArow)) * F_ + h * HD_ + dbase + pAk;
        size_t ga8 = ga + (size_t)8 * F_;
        pa.x = Qsrc[ga];  pa.y = Qsrc[ga8];  pa.z = Qsrc[ga + 4];  pa.w = Qsrc[ga8 + 4];
#pragma unroll
        for (int w = 0; w < 4; w++) {
            size_t gk = ((size_t)(b * LC_ + n0 + w * 32 + pBcol)) * F_ + h * HD_ + dbase + pAk;
            pb[w].x = Ksrc[gk];
            pb[w].y = Ksrc[gk + 4];
        }
    };
    auto store_s = [&]() {
        uint32_t hx = f2tf32(pa.x), hy = f2tf32(pa.y), hz = f2tf32(pa.z), hw = f2tf32(pa.w);
        sAh4[pg * 32 + pl] = make_uint4(hx, hy, hz, hw);
        sAl4[pg * 32 + pl] = make_uint4(
            f2tf32(pa.x - __uint_as_float(hx)), f2tf32(pa.y - __uint_as_float(hy)),
            f2tf32(pa.z - __uint_as_float(hz)), f2tf32(pa.w - __uint_as_float(hw)));
#pragma unroll
        for (int w = 0; w < 4; w++)
            sB2[(w * 8 + pg) * 32 + pl] = make_uint2(f2tf32(pb[w].x), f2tf32(pb[w].y));
    };

    load_g(0);
    store_s();
    __syncthreads();

    for (int k0 = 0; k0 < 128; k0 += 16) {
        const bool more = (k0 + 16 < 128);
        if (more) load_g(k0 + 16);

#pragma unroll
        for (int kcg = 0; kcg < 2; kcg++) {
            uint4 ah[2], al[2];
#pragma unroll
            for (int ma = 0; ma < 2; ma++) {
                ah[ma] = sAh4[(warpM * 4 + ma * 2 + kcg) * 32 + lane];
                al[ma] = sAl4[(warpM * 4 + ma * 2 + kcg) * 32 + lane];
            }
#pragma unroll
            for (int na = 0; na < 4; na++) {
                uint2 bb = sB2[(warpN * 8 + na * 2 + kcg) * 32 + lane];
#pragma unroll
                for (int ma = 0; ma < 2; ma++) {
                    mma_tf32(acc[ma][na], (const uint32_t*)&ah[ma], (const uint32_t*)&bb);
                    mma_tf32(acc[ma][na], (const uint32_t*)&al[ma], (const uint32_t*)&bb);
                }
            }
        }

        if (more) {
            __syncthreads();
            store_s();
            __syncthreads();
        }
    }

    float* Sdst = g_S + (size_t)(b * H_ + h) * S_ * LC_;
#pragma unroll
    for (int ma = 0; ma < 2; ma++) {
#pragma unroll
        for (int na = 0; na < 4; na++) {
#pragma unroll
            for (int c = 0; c < 4; c++) {
                int row = m0 + warpM * 32 + ma * 16 + qrow + ((c >= 2) ? 8 : 0);
                int col = n0 + warpN * 32 + na * 8 + qk * 2 + (c & 1);
                Sdst[(size_t)row * LC_ + col] = acc[ma][na][c] * 0.125f;
            }
        }
    }
}

// ---------------- softmax: one warp per row, row in registers ----------------
__global__ void __launch_bounds__(256) softmax_kernel(const float* __restrict__ mask)
{
    const int warp = threadIdx.x >> 5, lane = threadIdx.x & 31;
    const long long row = (long long)blockIdx.x * 8 + warp;
    const int b = (int)(row >> 15);
    float* Srow = g_S + row * LC_;

    float4 v[8];
    float mx = -1e30f;
#pragma unroll
    for (int j = 0; j < 8; j++) {
        int idx = lane * 4 + j * 128;
        v[j] = *(const float4*)&Srow[idx];
        if (mask) {
            float4 mk = *(const float4*)&mask[b * LC_ + idx];
            v[j].x += (1.0f - mk.x) * -1e9f;
            v[j].y += (1.0f - mk.y) * -1e9f;
            v[j].z += (1.0f - mk.z) * -1e9f;
            v[j].w += (1.0f - mk.w) * -1e9f;
        }
        mx = fmaxf(mx, fmaxf(fmaxf(v[j].x, v[j].y), fmaxf(v[j].z, v[j].w)));
    }
#pragma unroll
    for (int o = 16; o > 0; o >>= 1)
        mx = fmaxf(mx, __shfl_xor_sync(0xffffffffu, mx, o));

    float l = 0.0f;
#pragma unroll
    for (int j = 0; j < 8; j++) {
        v[j].x = __expf(v[j].x - mx);
        v[j].y = __expf(v[j].y - mx);
        v[j].z = __expf(v[j].z - mx);
        v[j].w = __expf(v[j].w - mx);
        l += v[j].x + v[j].y + v[j].z + v[j].w;
    }
#pragma unroll
    for (int o = 16; o > 0; o >>= 1)
        l += __shfl_xor_sync(0xffffffffu, l, o);
    float inv = 1.0f / l;

#pragma unroll
    for (int j = 0; j < 8; j++) {
        int idx = lane * 4 + j * 128;
        float4 p = v[j];
        p.x *= inv; p.y *= inv; p.z *= inv; p.w *= inv;
        *(float4*)&Srow[idx] = p;
    }
}

// ---------------- PV batched GEMM (packed): O = P @ [Vr|Vi], 3 chains ----------------
__global__ void __launch_bounds__(256, 2) pv_kernel()
{
    __shared__ uint4 sPh4[256], sPl4[256];
    __shared__ uint2 sBh2[1024], sBl2[1024];

    const int tid = threadIdx.x;
    const int warp = tid >> 5, lane = tid & 31;
    const int qrow = lane >> 2, qk = lane & 3;
    const int warpM = warp >> 2;
    const int warpN = warp & 3;
    const int m0 = blockIdx.y << 6;
    const int b  = blockIdx.z >> 4;
    const int h  = blockIdx.z & 15;

    const float* __restrict__ Psrc = g_S + (size_t)(b * H_ + h) * S_ * LC_;

    float acc[2][4][4] = {};

    const int pg = tid >> 5, pl = tid & 31;
    const int pqrow = pl >> 2, pqk = pl & 3;
    const int pArow = (pg >> 2) * 32 + ((pg >> 1) & 1) * 16 + pqrow;
    const int pAk   = (pg & 1) * 8 + pqk;
    const int pBcol = ((pg >> 1) & 3) * 8 + pqrow;

    float4 pa;
    float2 pb[4];

    auto load_g = [&](int k0) {
        size_t ga = (size_t)(m0 + pArow) * LC_ + k0 + pAk;
        size_t ga8 = ga + (size_t)8 * LC_;
        pa.x = Psrc[ga];  pa.y = Psrc[ga8];  pa.z = Psrc[ga + 4];  pa.w = Psrc[ga8 + 4];
#pragma unroll
        for (int w = 0; w < 4; w++) {
            int nb = w * 32 + pBcol;
            const float* __restrict__ Vsrc = (nb < 64) ? g_Vr : g_Vi;
            size_t gb = ((size_t)(b * LC_ + k0 + pAk)) * F_ + h * HD_ + (nb & 63);
            pb[w].x = Vsrc[gb];
            pb[w].y = Vsrc[gb + (size_t)4 * F_];
        }
    };
    auto store_s = [&]() {
        uint32_t hx = f2tf32(pa.x), hy = f2tf32(pa.y), hz = f2tf32(pa.z), hw = f2tf32(pa.w);
        sPh4[pg * 32 + pl] = make_uint4(hx, hy, hz, hw);
        sPl4[pg * 32 + pl] = make_uint4(
            f2tf32(pa.x - __uint_as_float(hx)), f2tf32(pa.y - __uint_as_float(hy)),
            f2tf32(pa.z - __uint_as_float(hz)), f2tf32(pa.w - __uint_as_float(hw)));
#pragma unroll
        for (int w = 0; w < 4; w++) {
            uint32_t bx = f2tf32(pb[w].x), by = f2tf32(pb[w].y);
            sBh2[(w * 8 + pg) * 32 + pl] = make_uint2(bx, by);
            sBl2[(w * 8 + pg) * 32 + pl] = make_uint2(
                f2tf32(pb[w].x - __uint_as_float(bx)), f2tf32(pb[w].y - __uint_as_float(by)));
        }
    };

    load_g(0);
    store_s();
    __syncthreads();

    for (int k0 = 0; k0 < LC_; k0 += 16) {
        const bool more = (k0 + 16 < LC_);
        if (more) load_g(k0 + 16);

#pragma unroll
        for (int kcg = 0; kcg < 2; kcg++) {
            uint4 ph[2], plr[2];
#pragma unroll
            for (int ma = 0; ma < 2; ma++) {
                ph[ma]  = sPh4[(warpM * 4 + ma * 2 + kcg) * 32 + lane];
                plr[ma] = sPl4[(warpM * 4 + ma * 2 + kcg) * 32 + lane];
            }
#pragma unroll
            for (int na = 0; na < 4; na++) {
                uint2 bh = sBh2[(warpN * 8 + na * 2 + kcg) * 32 + lane];
                uint2 bl = sBl2[(warpN * 8 + na * 2 + kcg) * 32 + lane];
#pragma unroll
                for (int ma = 0; ma < 2; ma++) {
                    mma_tf32(acc[ma][na], (const uint32_t*)&ph[ma],  (const uint32_t*)&bh);
                    mma_tf32(acc[ma][na], (const uint32_t*)&ph[ma],  (const uint32_t*)&bl);
                    mma_tf32(acc[ma][na], (const uint32_t*)&plr[ma], (const uint32_t*)&bh);
                }
            }
        }

        if (more) {
            __syncthreads();
            store_s();
            __syncthreads();
        }
    }

#pragma unroll
    for (int ma = 0; ma < 2; ma++) {
#pragma unroll
        for (int na = 0; na < 4; na++) {
#pragma unroll
            for (int c = 0; c < 4; c++) {
                int row = m0 + warpM * 32 + ma * 16 + qrow + ((c >= 2) ? 8 : 0);
                int col = warpN * 32 + na * 8 + qk * 2 + (c & 1);
                size_t g = ((size_t)(b * S_ + row)) * F_ + h * HD_ + (col & 63);
                if (col < 64) g_Or[g] = acc[ma][na][c];
                else          g_Oi[g] = acc[ma][na][c];
            }
        }
    }
}

// Fallback: bounded zero-fill so graph capture always has nodes.
__global__ void fill_zero_kernel(float* p, long long n)
{
    long long i = (long long)blockIdx.x * blockDim.x + threadIdx.x;
    if (i < n) p[i] = 0.0f;
}

// ---------------- launch ----------------
extern "C" void kernel_launch(void* const* d_in, const int* in_sizes, int n_in,
                              void* d_out, int out_size)
{
    const long long MN = (long long)B_ * S_ * F_;

    const float* x4M[2]  = {0, 0}; int n4M = 0;
    const float* xctx[2] = {0, 0}; int nctx = 0;
    const float* pmask   = 0;
    const float* wF[4]   = {0, 0, 0, 0}; int nwF = 0;
    const float* wC[4]   = {0, 0, 0, 0}; int nwC = 0;
    const float* bias[8] = {0, 0, 0, 0, 0, 0, 0, 0}; int nb = 0;

    for (int i = 0; i < n_in; i++) {
        const float* p = (const float*)d_in[i];
        long long sz = in_sizes[i];
        if (sz == (long long)B_ * S_ * F_)        { if (n4M < 2) x4M[n4M++] = p; }
        else if (sz == (long long)B_ * LC_ * DC_) { if (nctx < 2) xctx[nctx++] = p; }
        else if (sz == (long long)B_ * LC_)       { pmask = p; }
        else if (sz == (long long)F_ * F_)        { if (nwF < 4) wF[nwF++] = p; }
        else if (sz == (long long)DC_ * F_)       { if (nwC < 4) wC[nwC++] = p; }
        else if (sz == (long long)F_)             { if (nb < 8) bias[nb++] = p; }
    }

    const float* x_r = x4M[0],  *x_i = x4M[1];
    const float* ctx_r = xctx[0], *ctx_i = xctx[1];
    const float* Wqr = wF[0], *Wqi = wF[1], *Wor = wF[2], *Woi = wF[3];
    const float* Wkr = wC[0], *Wki = wC[1], *Wvr = wC[2], *Wvi = wC[3];
    const float* bqr = bias[0], *bqi = bias[1];
    const float* bkr = bias[2], *bki = bias[3];
    const float* bvr = bias[4], *bvi = bias[5];
    const float* bor = bias[6], *boi = bias[7];

    int omode = ((long long)out_size >= 2 * MN) ? 2 : 1;

    if (!x_r || !x_i || !ctx_r || !ctx_i || !Wqr || !Wqi || !Wor || !Woi ||
        !Wkr || !Wki || !Wvr || !Wvi) {
        long long n = (omode == 2) ? 2 * MN : MN;
        fill_zero_kernel<<<(unsigned)((n + 255) / 256), 256>>>((float*)d_out, n);
        return;
    }

    dim3 blk(256);

    // projections
    cgemm_kernel<0><<<dim3(F_ / 128, (B_ * S_) / 64), blk>>>(
        B_ * S_, F_, F_, x_r, x_i, Wqr, Wqi, bqr, bqi, nullptr, 0);
    cgemm_kernel<1><<<dim3(F_ / 128, (B_ * LC_) / 64), blk>>>(
        B_ * LC_, DC_, F_, ctx_r, ctx_i, Wkr, Wki, bkr, bki, nullptr, 0);
    cgemm_kernel<2><<<dim3(F_ / 128, (B_ * LC_) / 64), blk>>>(
        B_ * LC_, DC_, F_, ctx_r, ctx_i, Wvr, Wvi, bvr, bvi, nullptr, 0);

    // attention as 3 specialized kernels
    qk_kernel<<<dim3(LC_ / 128, S_ / 64, B_ * H_), blk>>>();
    softmax_kernel<<<(B_ * H_ * S_) / 8, blk>>>(pmask);
    pv_kernel<<<dim3(1, S_ / 64, B_ * H_), blk>>>();

    // output projection
    cgemm_kernel<3><<<dim3(F_ / 128, (B_ * S_) / 64), blk>>>(
        B_ * S_, F_, F_, nullptr, nullptr, Wor, Woi, bor, boi, (float*)d_out, omode);
}

// round 15
// speedup vs baseline: 1.1362x; 1.1362x over previous
#include <cuda_runtime.h>
#include <cuda_bf16.h>
#include <math.h>
#include <stdint.h>

#define B_   2
#define S_   2048
#define LC_  1024
#define F_   1024
#define DC_  768
#define H_   16
#define HD_  64

// ---------------- scratch (no allocation allowed; zero-initialized) ----------------
__device__ __align__(16) float g_Qr[(size_t)B_ * S_ * F_];
__device__ __align__(16) float g_Qi[(size_t)B_ * S_ * F_];
__device__ __align__(16) float g_Kr[(size_t)B_ * LC_ * F_];
__device__ __align__(16) float g_Ki[(size_t)B_ * LC_ * F_];
__device__ __align__(16) float g_Vr[(size_t)B_ * LC_ * F_];
__device__ __align__(16) float g_Vi[(size_t)B_ * LC_ * F_];
__device__ __align__(16) float g_Or[(size_t)B_ * S_ * F_];
__device__ __align__(16) float g_Oi[(size_t)B_ * S_ * F_];
__device__ __align__(16) float g_S [(size_t)B_ * H_ * S_ * LC_];   // scores -> probs

// ---------------- mma helpers ----------------
__device__ __forceinline__ uint32_t f2tf32(float x) {
    uint32_t r;
    asm("cvt.rna.tf32.f32 %0, %1;" : "=r"(r) : "f"(x));
    return r;
}

__device__ __forceinline__ void mma_tf32(float c[4], const uint32_t a[4], const uint32_t b[2]) {
    asm volatile(
        "mma.sync.aligned.m16n8k8.row.col.f32.tf32.tf32.f32 "
        "{%0,%1,%2,%3}, {%4,%5,%6,%7}, {%8,%9}, {%0,%1,%2,%3};"
        : "+f"(c[0]), "+f"(c[1]), "+f"(c[2]), "+f"(c[3])
        : "r"(a[0]), "r"(a[1]), "r"(a[2]), "r"(a[3]), "r"(b[0]), "r"(b[1]));
}

__device__ __forceinline__ void mma_bf16(float c[4], const uint32_t a[4], const uint32_t b[2]) {
    asm volatile(
        "mma.sync.aligned.m16n8k16.row.col.f32.bf16.bf16.f32 "
        "{%0,%1,%2,%3}, {%4,%5,%6,%7}, {%8,%9}, {%0,%1,%2,%3};"
        : "+f"(c[0]), "+f"(c[1]), "+f"(c[2]), "+f"(c[3])
        : "r"(a[0]), "r"(a[1]), "r"(a[2]), "r"(a[3]), "r"(b[0]), "r"(b[1]));
}

// pack two floats (k even, k odd) into bf16x2 hi-part word + lo-part word
__device__ __forceinline__ void pack_hilo(float x0, float x1, uint32_t& wh, uint32_t& wl) {
    __nv_bfloat16 h0 = __float2bfloat16(x0);
    __nv_bfloat16 h1 = __float2bfloat16(x1);
    __nv_bfloat16 l0 = __float2bfloat16(x0 - __bfloat162float(h0));
    __nv_bfloat16 l1 = __float2bfloat16(x1 - __bfloat162float(h1));
    __nv_bfloat162 hh = __nv_bfloat162(h0, h1);
    __nv_bfloat162 ll = __nv_bfloat162(l0, l1);
    wh = *(uint32_t*)&hh;
    wl = *(uint32_t*)&ll;
}

// ---------------- complex GEMM via tf32 tensor cores (R13 proven version) ----------------
#define SA_ST 20
#define SB_ST 136

template <int MODE>
__global__ void __launch_bounds__(256, 2) cgemm_kernel(
    int M, int K, int N,
    const float* __restrict__ Ap_r, const float* __restrict__ Ap_i,
    const float* __restrict__ Br, const float* __restrict__ Bi,
    const float* __restrict__ bbr, const float* __restrict__ bbi,
    float* __restrict__ outF, int omode)
{
    const float* __restrict__ Ar = (MODE == 3) ? g_Or : Ap_r;
    const float* __restrict__ Ai = (MODE == 3) ? g_Oi : Ap_i;

    __shared__ uint32_t sAr[64 * SA_ST];
    __shared__ uint32_t sAi[64 * SA_ST];
    __shared__ uint32_t sBr[16 * SB_ST];
    __shared__ uint32_t sBi[16 * SB_ST];
    __shared__ uint32_t sBni[16 * SB_ST];

    const int tid = threadIdx.x;
    const int warp = tid >> 5, lane = tid & 31;
    const int qrow = lane >> 2, qk = lane & 3;
    const int warpM = warp >> 2;
    const int warpN = warp & 3;
    const int m0 = blockIdx.y << 6;
    const int n0 = blockIdx.x << 7;

    float accr[2][4][4] = {};
    float acci[2][4][4] = {};

    const int lm = tid >> 4;
    const int lk = tid & 15;
    const int bn = tid & 127;
    const int bkb = tid >> 7;

    float pa_r[4], pa_i[4], pb_r[8], pb_i[8];

    auto load_g = [&](int k0) {
#pragma unroll
        for (int j = 0; j < 4; j++) {
            int m = lm + j * 16;
            size_t g = (size_t)(m0 + m) * K + (k0 + lk);
            pa_r[j] = Ar[g];
            pa_i[j] = Ai[g];
        }
#pragma unroll
        for (int j = 0; j < 8; j++) {
            int kk = bkb + j * 2;
            size_t g = (size_t)(k0 + kk) * N + (n0 + bn);
            pb_r[j] = Br[g];
            pb_i[j] = Bi[g];
        }
    };
    auto store_s = [&]() {
#pragma unroll
        for (int j = 0; j < 4; j++) {
            int m = lm + j * 16;
            sAr[m * SA_ST + lk] = f2tf32(pa_r[j]);
            sAi[m * SA_ST + lk] = f2tf32(pa_i[j]);
        }
#pragma unroll
        for (int j = 0; j < 8; j++) {
            int kk = bkb + j * 2;
            sBr[kk * SB_ST + bn]  = f2tf32(pb_r[j]);
            sBi[kk * SB_ST + bn]  = f2tf32(pb_i[j]);
            sBni[kk * SB_ST + bn] = f2tf32(-pb_i[j]);
        }
    };

    load_g(0);
    store_s();
    __syncthreads();

    for (int k0 = 0; k0 < K; k0 += 16) {
        const bool more = (k0 + 16 < K);
        if (more) load_g(k0 + 16);

#pragma unroll
        for (int kc = 0; kc < 16; kc += 8) {
            uint32_t ar[2][4], ai[2][4];
#pragma unroll
            for (int ma = 0; ma < 2; ma++) {
                int mb = warpM * 32 + ma * 16 + qrow;
                ar[ma][0] = sAr[(mb)     * SA_ST + kc + qk];
                ar[ma][1] = sAr[(mb + 8) * SA_ST + kc + qk];
                ar[ma][2] = sAr[(mb)     * SA_ST + kc + qk + 4];
                ar[ma][3] = sAr[(mb + 8) * SA_ST + kc + qk + 4];
                ai[ma][0] = sAi[(mb)     * SA_ST + kc + qk];
                ai[ma][1] = sAi[(mb + 8) * SA_ST + kc + qk];
                ai[ma][2] = sAi[(mb)     * SA_ST + kc + qk + 4];
                ai[ma][3] = sAi[(mb + 8) * SA_ST + kc + qk + 4];
            }
#pragma unroll
            for (int na = 0; na < 4; na++) {
                int nb = warpN * 32 + na * 8 + qrow;
                uint32_t br_[2], bi_[2], bni_[2];
                br_[0]  = sBr[(kc + qk)     * SB_ST + nb];
                br_[1]  = sBr[(kc + qk + 4) * SB_ST + nb];
                bi_[0]  = sBi[(kc + qk)     * SB_ST + nb];
                bi_[1]  = sBi[(kc + qk + 4) * SB_ST + nb];
                bni_[0] = sBni[(kc + qk)     * SB_ST + nb];
                bni_[1] = sBni[(kc + qk + 4) * SB_ST + nb];
#pragma unroll
                for (int ma = 0; ma < 2; ma++) {
                    mma_tf32(accr[ma][na], ar[ma], br_);
                    mma_tf32(accr[ma][na], ai[ma], bni_);
                    mma_tf32(acci[ma][na], ar[ma], bi_);
                    mma_tf32(acci[ma][na], ai[ma], br_);
                }
            }
        }

        if (more) {
            __syncthreads();
            store_s();
            __syncthreads();
        }
    }

#pragma unroll
    for (int ma = 0; ma < 2; ma++) {
#pragma unroll
        for (int na = 0; na < 4; na++) {
#pragma unroll
            for (int c = 0; c < 4; c++) {
                int row = m0 + warpM * 32 + ma * 16 + qrow + ((c >= 2) ? 8 : 0);
                int col = n0 + warpN * 32 + na * 8 + qk * 2 + (c & 1);
                float vr = accr[ma][na][c] + (bbr ? bbr[col] : 0.0f);
                float vi = acci[ma][na][c] + (bbi ? bbi[col] : 0.0f);
                size_t idx = (size_t)row * N + col;
                if (MODE == 0)      { g_Qr[idx] = vr; g_Qi[idx] = vi; }
                else if (MODE == 1) { g_Kr[idx] = vr; g_Ki[idx] = vi; }
                else if (MODE == 2) { g_Vr[idx] = vr; g_Vi[idx] = vi; }
                else {
                    if (omode == 2) { outF[2 * idx] = vr; outF[2 * idx + 1] = vi; }
                    else            { outF[idx] = vr; }
                }
            }
        }
    }
}

// ---------------- QK batched GEMM (bf16 hi/lo 3-chain, m16n8k16) ----------------
// S = (Qr.Kr^T + Qi.Ki^T)*scale. Virtual K = 128. Block 64m x 128n, 8 warps 32x32.
// Words pack k-pairs: w(row,kp) = bf16x2(x[2kp], x[2kp+1]). Stride 12 (conflict-free).
#define WST 12

__global__ void __launch_bounds__(256, 2) qk_kernel()
{
    __shared__ uint32_t sAh[64 * WST], sAl[64 * WST];
    __shared__ uint32_t sBh[128 * WST], sBl[128 * WST];

    const int tid = threadIdx.x;
    const int warp = tid >> 5, lane = tid & 31;
    const int qrow = lane >> 2, qk = lane & 3;
    const int warpM = warp >> 2;
    const int warpN = warp & 3;
    const int m0 = blockIdx.y << 6;
    const int n0 = blockIdx.x << 7;
    const int b  = blockIdx.z >> 4;
    const int h  = blockIdx.z & 15;

    float acc[2][4][4] = {};

    // producers: A: row = tid>>2, words pw & pw+4 ; B: col = tid>>1, words pwb..pwb+3
    const int prow = tid >> 2, pw = tid & 3;
    const int pcol = tid >> 1, pwb = (tid & 1) * 4;

    float2 pa0, pa1;
    float4 pb0, pb1;

    auto load_g = [&](int k0) {
        const float* __restrict__ Qsrc = (k0 < 64) ? g_Qr : g_Qi;
        const float* __restrict__ Ksrc = (k0 < 64) ? g_Kr : g_Ki;
        const int dbase = (k0 & 63);
        size_t ga = ((size_t)(b * S_ + m0 + prow)) * F_ + h * HD_ + dbase + 2 * pw;
        pa0 = *(const float2*)&Qsrc[ga];
        pa1 = *(const float2*)&Qsrc[ga + 8];
        size_t gb = ((size_t)(b * LC_ + n0 + pcol)) * F_ + h * HD_ + dbase + 2 * pwb;
        pb0 = *(const float4*)&Ksrc[gb];
        pb1 = *(const float4*)&Ksrc[gb + 4];
    };
    auto store_s = [&]() {
        uint32_t wh, wl;
        pack_hilo(pa0.x, pa0.y, wh, wl);
        sAh[prow * WST + pw] = wh;  sAl[prow * WST + pw] = wl;
        pack_hilo(pa1.x, pa1.y, wh, wl);
        sAh[prow * WST + pw + 4] = wh;  sAl[prow * WST + pw + 4] = wl;
        float f[8] = {pb0.x, pb0.y, pb0.z, pb0.w, pb1.x, pb1.y, pb1.z, pb1.w};
#pragma unroll
        for (int j = 0; j < 4; j++) {
            pack_hilo(f[2 * j], f[2 * j + 1], wh, wl);
            sBh[pcol * WST + pwb + j] = wh;
            sBl[pcol * WST + pwb + j] = wl;
        }
    };

    load_g(0);
    store_s();
    __syncthreads();

    for (int k0 = 0; k0 < 128; k0 += 16) {
        const bool more = (k0 + 16 < 128);
        if (more) load_g(k0 + 16);

        uint32_t ah[2][4], al[2][4];
#pragma unroll
        for (int ma = 0; ma < 2; ma++) {
            int mb = warpM * 32 + ma * 16 + qrow;
            ah[ma][0] = sAh[(mb)     * WST + qk];
            ah[ma][1] = sAh[(mb + 8) * WST + qk];
            ah[ma][2] = sAh[(mb)     * WST + qk + 4];
            ah[ma][3] = sAh[(mb + 8) * WST + qk + 4];
            al[ma][0] = sAl[(mb)     * WST + qk];
            al[ma][1] = sAl[(mb + 8) * WST + qk];
            al[ma][2] = sAl[(mb)     * WST + qk + 4];
            al[ma][3] = sAl[(mb + 8) * WST + qk + 4];
        }
#pragma unroll
        for (int na = 0; na < 4; na++) {
            int nb = warpN * 32 + na * 8 + qrow;
            uint32_t bh[2], bl[2];
            bh[0] = sBh[nb * WST + qk];
            bh[1] = sBh[nb * WST + qk + 4];
            bl[0] = sBl[nb * WST + qk];
            bl[1] = sBl[nb * WST + qk + 4];
#pragma unroll
            for (int ma = 0; ma < 2; ma++) {
                mma_bf16(acc[ma][na], ah[ma], bh);
                mma_bf16(acc[ma][na], al[ma], bh);
                mma_bf16(acc[ma][na], ah[ma], bl);
            }
        }

        if (more) {
            __syncthreads();
            store_s();
            __syncthreads();
        }
    }

    float* Sdst = g_S + (size_t)(b * H_ + h) * S_ * LC_;
#pragma unroll
    for (int ma = 0; ma < 2; ma++) {
#pragma unroll
        for (int na = 0; na < 4; na++) {
#pragma unroll
            for (int c = 0; c < 4; c++) {
                int row = m0 + warpM * 32 + ma * 16 + qrow + ((c >= 2) ? 8 : 0);
                int col = n0 + warpN * 32 + na * 8 + qk * 2 + (c & 1);
                Sdst[(size_t)row * LC_ + col] = acc[ma][na][c] * 0.125f;
            }
        }
    }
}

// ---------------- softmax: one warp per row, row in registers ----------------
__global__ void __launch_bounds__(256) softmax_kernel(const float* __restrict__ mask)
{
    const int warp = threadIdx.x >> 5, lane = threadIdx.x & 31;
    const long long row = (long long)blockIdx.x * 8 + warp;
    const int b = (int)(row >> 15);
    float* Srow = g_S + row * LC_;

    float4 v[8];
    float mx = -1e30f;
#pragma unroll
    for (int j = 0; j < 8; j++) {
        int idx = lane * 4 + j * 128;
        v[j] = *(const float4*)&Srow[idx];
        if (mask) {
            float4 mk = *(const float4*)&mask[b * LC_ + idx];
            v[j].x += (1.0f - mk.x) * -1e9f;
            v[j].y += (1.0f - mk.y) * -1e9f;
            v[j].z += (1.0f - mk.z) * -1e9f;
            v[j].w += (1.0f - mk.w) * -1e9f;
        }
        mx = fmaxf(mx, fmaxf(fmaxf(v[j].x, v[j].y), fmaxf(v[j].z, v[j].w)));
    }
#pragma unroll
    for (int o = 16; o > 0; o >>= 1)
        mx = fmaxf(mx, __shfl_xor_sync(0xffffffffu, mx, o));

    float l = 0.0f;
#pragma unroll
    for (int j = 0; j < 8; j++) {
        v[j].x = __expf(v[j].x - mx);
        v[j].y = __expf(v[j].y - mx);
        v[j].z = __expf(v[j].z - mx);
        v[j].w = __expf(v[j].w - mx);
        l += v[j].x + v[j].y + v[j].z + v[j].w;
    }
#pragma unroll
    for (int o = 16; o > 0; o >>= 1)
        l += __shfl_xor_sync(0xffffffffu, l, o);
    float inv = 1.0f / l;

#pragma unroll
    for (int j = 0; j < 8; j++) {
        int idx = lane * 4 + j * 128;
        float4 p = v[j];
        p.x *= inv; p.y *= inv; p.z *= inv; p.w *= inv;
        *(float4*)&Srow[idx] = p;
    }
}

// ---------------- PV batched GEMM (bf16 hi/lo 3-chain): O = P @ [Vr|Vi] ----------------
// Per batch (b,h): M=S_, N=128, K=LC_. Block 64m x 128n, k16 steps.
__global__ void __launch_bounds__(256, 2) pv_kernel()
{
    __shared__ uint32_t sAh[64 * WST], sAl[64 * WST];
    __shared__ uint32_t sBh[128 * WST], sBl[128 * WST];

    const int tid = threadIdx.x;
    const int warp = tid >> 5, lane = tid & 31;
    const int qrow = lane >> 2, qk = lane & 3;
    const int warpM = warp >> 2;
    const int warpN = warp & 3;
    const int m0 = blockIdx.y << 6;
    const int b  = blockIdx.z >> 4;
    const int h  = blockIdx.z & 15;

    const float* __restrict__ Psrc = g_S + (size_t)(b * H_ + h) * S_ * LC_;

    float acc[2][4][4] = {};

    const int prow = tid >> 2, pw = tid & 3;
    const int pcol = tid >> 1, pwb = (tid & 1) * 4;
    const float* __restrict__ Vsrc = (pcol < 64) ? g_Vr : g_Vi;
    const int vd = pcol & 63;

    float2 pa0, pa1;
    float pv_[8];

    auto load_g = [&](int k0) {
        size_t ga = (size_t)(m0 + prow) * LC_ + k0 + 2 * pw;
        pa0 = *(const float2*)&Psrc[ga];
        pa1 = *(const float2*)&Psrc[ga + 8];
#pragma unroll
        for (int j = 0; j < 8; j++) {
            int k = k0 + 2 * pwb + j;
            pv_[j] = Vsrc[((size_t)(b * LC_ + k)) * F_ + h * HD_ + vd];
        }
    };
    auto store_s = [&]() {
        uint32_t wh, wl;
        pack_hilo(pa0.x, pa0.y, wh, wl);
        sAh[prow * WST + pw] = wh;  sAl[prow * WST + pw] = wl;
        pack_hilo(pa1.x, pa1.y, wh, wl);
        sAh[prow * WST + pw + 4] = wh;  sAl[prow * WST + pw + 4] = wl;
#pragma unroll
        for (int j = 0; j < 4; j++) {
            pack_hilo(pv_[2 * j], pv_[2 * j + 1], wh, wl);
            sBh[pcol * WST + pwb + j] = wh;
            sBl[pcol * WST + pwb + j] = wl;
        }
    };

    load_g(0);
    store_s();
    __syncthreads();

    for (int k0 = 0; k0 < LC_; k0 += 16) {
        const bool more = (k0 + 16 < LC_);
        if (more) load_g(k0 + 16);

        uint32_t ah[2][4], al[2][4];
#pragma unroll
        for (int ma = 0; ma < 2; ma++) {
            int mb = warpM * 32 + ma * 16 + qrow;
            ah[ma][0] = sAh[(mb)     * WST + qk];
            ah[ma][1] = sAh[(mb + 8) * WST + qk];
            ah[ma][2] = sAh[(mb)     * WST + qk + 4];
            ah[ma][3] = sAh[(mb + 8) * WST + qk + 4];
            al[ma][0] = sAl[(mb)     * WST + qk];
            al[ma][1] = sAl[(mb + 8) * WST + qk];
            al[ma][2] = sAl[(mb)     * WST + qk + 4];
            al[ma][3] = sAl[(mb + 8) * WST + qk + 4];
        }
#pragma unroll
        for (int na = 0; na < 4; na++) {
            int nb = warpN * 32 + na * 8 + qrow;
            uint32_t bh[2], bl[2];
            bh[0] = sBh[nb * WST + qk];
            bh[1] = sBh[nb * WST + qk + 4];
            bl[0] = sBl[nb * WST + qk];
            bl[1] = sBl[nb * WST + qk + 4];
#pragma unroll
            for (int ma = 0; ma < 2; ma++) {
                mma_bf16(acc[ma][na], ah[ma], bh);
                mma_bf16(acc[ma][na], al[ma], bh);
                mma_bf16(acc[ma][na], ah[ma], bl);
            }
        }

        if (more) {
            __syncthreads();
            store_s();
            __syncthreads();
        }
    }

#pragma unroll
    for (int ma = 0; ma < 2; ma++) {
#pragma unroll
        for (int na = 0; na < 4; na++) {
#pragma unroll
            for (int c = 0; c < 4; c++) {
                int row = m0 + warpM * 32 + ma * 16 + qrow + ((c >= 2) ? 8 : 0);
                int col = warpN * 32 + na * 8 + qk * 2 + (c & 1);
                size_t g = ((size_t)(b * S_ + row)) * F_ + h * HD_ + (col & 63);
                if (col < 64) g_Or[g] = acc[ma][na][c];
                else          g_Oi[g] = acc[ma][na][c];
            }
        }
    }
}

// Fallback: bounded zero-fill so graph capture always has nodes.
__global__ void fill_zero_kernel(float* p, long long n)
{
    long long i = (long long)blockIdx.x * blockDim.x + threadIdx.x;
    if (i < n) p[i] = 0.0f;
}

// ---------------- launch ----------------
extern "C" void kernel_launch(void* const* d_in, const int* in_sizes, int n_in,
                              void* d_out, int out_size)
{
    const long long MN = (long long)B_ * S_ * F_;

    const float* x4M[2]  = {0, 0}; int n4M = 0;
    const float* xctx[2] = {0, 0}; int nctx = 0;
    const float* pmask   = 0;
    const float* wF[4]   = {0, 0, 0, 0}; int nwF = 0;
    const float* wC[4]   = {0, 0, 0, 0}; int nwC = 0;
    const float* bias[8] = {0, 0, 0, 0, 0, 0, 0, 0}; int nb = 0;

    for (int i = 0; i < n_in; i++) {
        const float* p = (const float*)d_in[i];
        long long sz = in_sizes[i];
        if (sz == (long long)B_ * S_ * F_)        { if (n4M < 2) x4M[n4M++] = p; }
        else if (sz == (long long)B_ * LC_ * DC_) { if (nctx < 2) xctx[nctx++] = p; }
        else if (sz == (long long)B_ * LC_)       { pmask = p; }
        else if (sz == (long long)F_ * F_)        { if (nwF < 4) wF[nwF++] = p; }
        else if (sz == (long long)DC_ * F_)       { if (nwC < 4) wC[nwC++] = p; }
        else if (sz == (long long)F_)             { if (nb < 8) bias[nb++] = p; }
    }

    const float* x_r = x4M[0],  *x_i = x4M[1];
    const float* ctx_r = xctx[0], *ctx_i = xctx[1];
    const float* Wqr = wF[0], *Wqi = wF[1], *Wor = wF[2], *Woi = wF[3];
    const float* Wkr = wC[0], *Wki = wC[1], *Wvr = wC[2], *Wvi = wC[3];
    const float* bqr = bias[0], *bqi = bias[1];
    const float* bkr = bias[2], *bki = bias[3];
    const float* bvr = bias[4], *bvi = bias[5];
    const float* bor = bias[6], *boi = bias[7];

    int omode = ((long long)out_size >= 2 * MN) ? 2 : 1;

    if (!x_r || !x_i || !ctx_r || !ctx_i || !Wqr || !Wqi || !Wor || !Woi ||
        !Wkr || !Wki || !Wvr || !Wvi) {
        long long n = (omode == 2) ? 2 * MN : MN;
        fill_zero_kernel<<<(unsigned)((n + 255) / 256), 256>>>((float*)d_out, n);
        return;
    }

    dim3 blk(256);

    // projections
    cgemm_kernel<0><<<dim3(F_ / 128, (B_ * S_) / 64), blk>>>(
        B_ * S_, F_, F_, x_r, x_i, Wqr, Wqi, bqr, bqi, nullptr, 0);
    cgemm_kernel<1><<<dim3(F_ / 128, (B_ * LC_) / 64), blk>>>(
        B_ * LC_, DC_, F_, ctx_r, ctx_i, Wkr, Wki, bkr, bki, nullptr, 0);
    cgemm_kernel<2><<<dim3(F_ / 128, (B_ * LC_) / 64), blk>>>(
        B_ * LC_, DC_, F_, ctx_r, ctx_i, Wvr, Wvi, bvr, bvi, nullptr, 0);

    // attention as 3 specialized kernels
    qk_kernel<<<dim3(LC_ / 128, S_ / 64, B_ * H_), blk>>>();
    softmax_kernel<<<(B_ * H_ * S_) / 8, blk>>>(pmask);
    pv_kernel<<<dim3(1, S_ / 64, B_ * H_), blk>>>();

    // output projection
    cgemm_kernel<3><<<dim3(F_ / 128, (B_ * S_) / 64), blk>>>(
        B_ * S_, F_, F_, nullptr, nullptr, Wor, Woi, bor, boi, (float*)d_out, omode);
}

// round 16
// speedup vs baseline: 1.1468x; 1.0094x over previous
#include <cuda_runtime.h>
#include <cuda_bf16.h>
#include <math.h>
#include <stdint.h>

#define B_   2
#define S_   2048
#define LC_  1024
#define F_   1024
#define DC_  768
#define H_   16
#define HD_  64

// ---------------- scratch (no allocation allowed; zero-initialized) ----------------
__device__ __align__(16) float g_Qr[(size_t)B_ * S_ * F_];
__device__ __align__(16) float g_Qi[(size_t)B_ * S_ * F_];
__device__ __align__(16) float g_Kr[(size_t)B_ * LC_ * F_];
__device__ __align__(16) float g_Ki[(size_t)B_ * LC_ * F_];
__device__ __align__(16) float g_Vr[(size_t)B_ * LC_ * F_];
__device__ __align__(16) float g_Vi[(size_t)B_ * LC_ * F_];
__device__ __align__(16) float g_Or[(size_t)B_ * S_ * F_];
__device__ __align__(16) float g_Oi[(size_t)B_ * S_ * F_];
__device__ __align__(16) float g_S [(size_t)B_ * H_ * S_ * LC_];   // scores -> probs

// ---------------- mma helpers ----------------
__device__ __forceinline__ uint32_t f2tf32(float x) {
    uint32_t r;
    asm("cvt.rna.tf32.f32 %0, %1;" : "=r"(r) : "f"(x));
    return r;
}

__device__ __forceinline__ void mma_tf32(float c[4], const uint32_t a[4], const uint32_t b[2]) {
    asm volatile(
        "mma.sync.aligned.m16n8k8.row.col.f32.tf32.tf32.f32 "
        "{%0,%1,%2,%3}, {%4,%5,%6,%7}, {%8,%9}, {%0,%1,%2,%3};"
        : "+f"(c[0]), "+f"(c[1]), "+f"(c[2]), "+f"(c[3])
        : "r"(a[0]), "r"(a[1]), "r"(a[2]), "r"(a[3]), "r"(b[0]), "r"(b[1]));
}

__device__ __forceinline__ void mma_bf16(float c[4], const uint32_t a[4], const uint32_t b[2]) {
    asm volatile(
        "mma.sync.aligned.m16n8k16.row.col.f32.bf16.bf16.f32 "
        "{%0,%1,%2,%3}, {%4,%5,%6,%7}, {%8,%9}, {%0,%1,%2,%3};"
        : "+f"(c[0]), "+f"(c[1]), "+f"(c[2]), "+f"(c[3])
        : "r"(a[0]), "r"(a[1]), "r"(a[2]), "r"(a[3]), "r"(b[0]), "r"(b[1]));
}

// pack two floats (k even, k odd) into bf16x2 hi-part word + lo-part word
__device__ __forceinline__ void pack_hilo(float x0, float x1, uint32_t& wh, uint32_t& wl) {
    __nv_bfloat16 h0 = __float2bfloat16(x0);
    __nv_bfloat16 h1 = __float2bfloat16(x1);
    __nv_bfloat16 l0 = __float2bfloat16(x0 - __bfloat162float(h0));
    __nv_bfloat16 l1 = __float2bfloat16(x1 - __bfloat162float(h1));
    __nv_bfloat162 hh = __nv_bfloat162(h0, h1);
    __nv_bfloat162 ll = __nv_bfloat162(l0, l1);
    wh = *(uint32_t*)&hh;
    wl = *(uint32_t*)&ll;
}

// ---------------- complex GEMM via tf32 (double-buffered dynamic smem) ----------------
#define SA_ST 20
#define SB_ST 136
#define CG_A_WORDS (64 * SA_ST)            // 1280
#define CG_B_WORDS (16 * SB_ST)            // 2176
#define CG_BUF_WORDS (2 * CG_A_WORDS + 3 * CG_B_WORDS)   // 9088
#define CG_SMEM_BYTES (2 * CG_BUF_WORDS * 4)             // 72704

template <int MODE>
__global__ void __launch_bounds__(256, 2) cgemm_kernel(
    int M, int K, int N,
    const float* __restrict__ Ap_r, const float* __restrict__ Ap_i,
    const float* __restrict__ Br, const float* __restrict__ Bi,
    const float* __restrict__ bbr, const float* __restrict__ bbi,
    float* __restrict__ outF, int omode)
{
    const float* __restrict__ Ar = (MODE == 3) ? g_Or : Ap_r;
    const float* __restrict__ Ai = (MODE == 3) ? g_Oi : Ap_i;

    extern __shared__ uint32_t dsm[];

    const int tid = threadIdx.x;
    const int warp = tid >> 5, lane = tid & 31;
    const int qrow = lane >> 2, qk = lane & 3;
    const int warpM = warp >> 2;
    const int warpN = warp & 3;
    const int m0 = blockIdx.y << 6;
    const int n0 = blockIdx.x << 7;

    float accr[2][4][4] = {};
    float acci[2][4][4] = {};

    const int lm = tid >> 4;
    const int lk = tid & 15;
    const int bn = tid & 127;
    const int bkb = tid >> 7;

    float pa_r[4], pa_i[4], pb_r[8], pb_i[8];

    auto load_g = [&](int k0) {
#pragma unroll
        for (int j = 0; j < 4; j++) {
            int m = lm + j * 16;
            size_t g = (size_t)(m0 + m) * K + (k0 + lk);
            pa_r[j] = Ar[g];
            pa_i[j] = Ai[g];
        }
#pragma unroll
        for (int j = 0; j < 8; j++) {
            int kk = bkb + j * 2;
            size_t g = (size_t)(k0 + kk) * N + (n0 + bn);
            pb_r[j] = Br[g];
            pb_i[j] = Bi[g];
        }
    };
    auto store_s = [&](int par) {
        uint32_t* base = dsm + par * CG_BUF_WORDS;
        uint32_t* bAr = base;
        uint32_t* bAi = base + CG_A_WORDS;
        uint32_t* bBr = base + 2 * CG_A_WORDS;
        uint32_t* bBi = bBr + CG_B_WORDS;
        uint32_t* bBni = bBi + CG_B_WORDS;
#pragma unroll
        for (int j = 0; j < 4; j++) {
            int m = lm + j * 16;
            bAr[m * SA_ST + lk] = f2tf32(pa_r[j]);
            bAi[m * SA_ST + lk] = f2tf32(pa_i[j]);
        }
#pragma unroll
        for (int j = 0; j < 8; j++) {
            int kk = bkb + j * 2;
            bBr[kk * SB_ST + bn]  = f2tf32(pb_r[j]);
            bBi[kk * SB_ST + bn]  = f2tf32(pb_i[j]);
            bBni[kk * SB_ST + bn] = f2tf32(-pb_i[j]);
        }
    };

    load_g(0);
    store_s(0);
    __syncthreads();

    const int T = K / 16;
    for (int t = 0; t < T; t++) {
        const bool more = (t + 1 < T);
        if (more) load_g((t + 1) * 16);

        uint32_t* base = dsm + (t & 1) * CG_BUF_WORDS;
        uint32_t* bAr = base;
        uint32_t* bAi = base + CG_A_WORDS;
        uint32_t* bBr = base + 2 * CG_A_WORDS;
        uint32_t* bBi = bBr + CG_B_WORDS;
        uint32_t* bBni = bBi + CG_B_WORDS;

#pragma unroll
        for (int kc = 0; kc < 16; kc += 8) {
            uint32_t ar[2][4], ai[2][4];
#pragma unroll
            for (int ma = 0; ma < 2; ma++) {
                int mb = warpM * 32 + ma * 16 + qrow;
                ar[ma][0] = bAr[(mb)     * SA_ST + kc + qk];
                ar[ma][1] = bAr[(mb + 8) * SA_ST + kc + qk];
                ar[ma][2] = bAr[(mb)     * SA_ST + kc + qk + 4];
                ar[ma][3] = bAr[(mb + 8) * SA_ST + kc + qk + 4];
                ai[ma][0] = bAi[(mb)     * SA_ST + kc + qk];
                ai[ma][1] = bAi[(mb + 8) * SA_ST + kc + qk];
                ai[ma][2] = bAi[(mb)     * SA_ST + kc + qk + 4];
                ai[ma][3] = bAi[(mb + 8) * SA_ST + kc + qk + 4];
            }
#pragma unroll
            for (int na = 0; na < 4; na++) {
                int nb = warpN * 32 + na * 8 + qrow;
                uint32_t br_[2], bi_[2], bni_[2];
                br_[0]  = bBr[(kc + qk)     * SB_ST + nb];
                br_[1]  = bBr[(kc + qk + 4) * SB_ST + nb];
                bi_[0]  = bBi[(kc + qk)     * SB_ST + nb];
                bi_[1]  = bBi[(kc + qk + 4) * SB_ST + nb];
                bni_[0] = bBni[(kc + qk)     * SB_ST + nb];
                bni_[1] = bBni[(kc + qk + 4) * SB_ST + nb];
#pragma unroll
                for (int ma = 0; ma < 2; ma++) {
                    mma_tf32(accr[ma][na], ar[ma], br_);
                    mma_tf32(accr[ma][na], ai[ma], bni_);
                    mma_tf32(acci[ma][na], ar[ma], bi_);
                    mma_tf32(acci[ma][na], ai[ma], br_);
                }
            }
        }

        if (more) {
            store_s((t + 1) & 1);   // opposite buffer: safe vs in-flight mma readers
            __syncthreads();        // ONE barrier per iteration
        }
    }

#pragma unroll
    for (int ma = 0; ma < 2; ma++) {
#pragma unroll
        for (int na = 0; na < 4; na++) {
#pragma unroll
            for (int c = 0; c < 4; c++) {
                int row = m0 + warpM * 32 + ma * 16 + qrow + ((c >= 2) ? 8 : 0);
                int col = n0 + warpN * 32 + na * 8 + qk * 2 + (c & 1);
                float vr = accr[ma][na][c] + (bbr ? bbr[col] : 0.0f);
                float vi = acci[ma][na][c] + (bbi ? bbi[col] : 0.0f);
                size_t idx = (size_t)row * N + col;
                if (MODE == 0)      { g_Qr[idx] = vr; g_Qi[idx] = vi; }
                else if (MODE == 1) { g_Kr[idx] = vr; g_Ki[idx] = vi; }
                else if (MODE == 2) { g_Vr[idx] = vr; g_Vi[idx] = vi; }
                else {
                    if (omode == 2) { outF[2 * idx] = vr; outF[2 * idx + 1] = vi; }
                    else            { outF[idx] = vr; }
                }
            }
        }
    }
}

// ---------------- QK batched GEMM (bf16 hi/lo 3-chain, double-buffered) ----------------
#define WST 12

__global__ void __launch_bounds__(256, 2) qk_kernel()
{
    __shared__ uint32_t sAh[2][64 * WST], sAl[2][64 * WST];
    __shared__ uint32_t sBh[2][128 * WST], sBl[2][128 * WST];

    const int tid = threadIdx.x;
    const int warp = tid >> 5, lane = tid & 31;
    const int qrow = lane >> 2, qk = lane & 3;
    const int warpM = warp >> 2;
    const int warpN = warp & 3;
    const int m0 = blockIdx.y << 6;
    const int n0 = blockIdx.x << 7;
    const int b  = blockIdx.z >> 4;
    const int h  = blockIdx.z & 15;

    float acc[2][4][4] = {};

    const int prow = tid >> 2, pw = tid & 3;
    const int pcol = tid >> 1, pwb = (tid & 1) * 4;

    float2 pa0, pa1;
    float4 pb0, pb1;

    auto load_g = [&](int k0) {
        const float* __restrict__ Qsrc = (k0 < 64) ? g_Qr : g_Qi;
        const float* __restrict__ Ksrc = (k0 < 64) ? g_Kr : g_Ki;
        const int dbase = (k0 & 63);
        size_t ga = ((size_t)(b * S_ + m0 + prow)) * F_ + h * HD_ + dbase + 2 * pw;
        pa0 = *(const float2*)&Qsrc[ga];
        pa1 = *(const float2*)&Qsrc[ga + 8];
        size_t gb = ((size_t)(b * LC_ + n0 + pcol)) * F_ + h * HD_ + dbase + 2 * pwb;
        pb0 = *(const float4*)&Ksrc[gb];
        pb1 = *(const float4*)&Ksrc[gb + 4];
    };
    auto store_s = [&](int par) {
        uint32_t wh, wl;
        pack_hilo(pa0.x, pa0.y, wh, wl);
        sAh[par][prow * WST + pw] = wh;  sAl[par][prow * WST + pw] = wl;
        pack_hilo(pa1.x, pa1.y, wh, wl);
        sAh[par][prow * WST + pw + 4] = wh;  sAl[par][prow * WST + pw + 4] = wl;
        float f[8] = {pb0.x, pb0.y, pb0.z, pb0.w, pb1.x, pb1.y, pb1.z, pb1.w};
#pragma unroll
        for (int j = 0; j < 4; j++) {
            pack_hilo(f[2 * j], f[2 * j + 1], wh, wl);
            sBh[par][pcol * WST + pwb + j] = wh;
            sBl[par][pcol * WST + pwb + j] = wl;
        }
    };

    load_g(0);
    store_s(0);
    __syncthreads();

    for (int t = 0; t < 8; t++) {
        const bool more = (t + 1 < 8);
        if (more) load_g((t + 1) * 16);
        const int par = t & 1;

        uint32_t ah[2][4], al[2][4];
#pragma unroll
        for (int ma = 0; ma < 2; ma++) {
            int mb = warpM * 32 + ma * 16 + qrow;
            ah[ma][0] = sAh[par][(mb)     * WST + qk];
            ah[ma][1] = sAh[par][(mb + 8) * WST + qk];
            ah[ma][2] = sAh[par][(mb)     * WST + qk + 4];
            ah[ma][3] = sAh[par][(mb + 8) * WST + qk + 4];
            al[ma][0] = sAl[par][(mb)     * WST + qk];
            al[ma][1] = sAl[par][(mb + 8) * WST + qk];
            al[ma][2] = sAl[par][(mb)     * WST + qk + 4];
            al[ma][3] = sAl[par][(mb + 8) * WST + qk + 4];
        }
#pragma unroll
        for (int na = 0; na < 4; na++) {
            int nb = warpN * 32 + na * 8 + qrow;
            uint32_t bh[2], bl[2];
            bh[0] = sBh[par][nb * WST + qk];
            bh[1] = sBh[par][nb * WST + qk + 4];
            bl[0] = sBl[par][nb * WST + qk];
            bl[1] = sBl[par][nb * WST + qk + 4];
#pragma unroll
            for (int ma = 0; ma < 2; ma++) {
                mma_bf16(acc[ma][na], ah[ma], bh);
                mma_bf16(acc[ma][na], al[ma], bh);
                mma_bf16(acc[ma][na], ah[ma], bl);
            }
        }

        if (more) {
            store_s(1 - par);
            __syncthreads();
        }
    }

    float* Sdst = g_S + (size_t)(b * H_ + h) * S_ * LC_;
#pragma unroll
    for (int ma = 0; ma < 2; ma++) {
#pragma unroll
        for (int na = 0; na < 4; na++) {
#pragma unroll
            for (int c = 0; c < 4; c++) {
                int row = m0 + warpM * 32 + ma * 16 + qrow + ((c >= 2) ? 8 : 0);
                int col = n0 + warpN * 32 + na * 8 + qk * 2 + (c & 1);
                Sdst[(size_t)row * LC_ + col] = acc[ma][na][c] * 0.125f;
            }
        }
    }
}

// ---------------- softmax: one warp per row, row in registers ----------------
__global__ void __launch_bounds__(256) softmax_kernel(const float* __restrict__ mask)
{
    const int warp = threadIdx.x >> 5, lane = threadIdx.x & 31;
    const long long row = (long long)blockIdx.x * 8 + warp;
    const int b = (int)(row >> 15);
    float* Srow = g_S + row * LC_;

    float4 v[8];
    float mx = -1e30f;
#pragma unroll
    for (int j = 0; j < 8; j++) {
        int idx = lane * 4 + j * 128;
        v[j] = *(const float4*)&Srow[idx];
        if (mask) {
            float4 mk = *(const float4*)&mask[b * LC_ + idx];
            v[j].x += (1.0f - mk.x) * -1e9f;
            v[j].y += (1.0f - mk.y) * -1e9f;
            v[j].z += (1.0f - mk.z) * -1e9f;
            v[j].w += (1.0f - mk.w) * -1e9f;
        }
        mx = fmaxf(mx, fmaxf(fmaxf(v[j].x, v[j].y), fmaxf(v[j].z, v[j].w)));
    }
#pragma unroll
    for (int o = 16; o > 0; o >>= 1)
        mx = fmaxf(mx, __shfl_xor_sync(0xffffffffu, mx, o));

    float l = 0.0f;
#pragma unroll
    for (int j = 0; j < 8; j++) {
        v[j].x = __expf(v[j].x - mx);
        v[j].y = __expf(v[j].y - mx);
        v[j].z = __expf(v[j].z - mx);
        v[j].w = __expf(v[j].w - mx);
        l += v[j].x + v[j].y + v[j].z + v[j].w;
    }
#pragma unroll
    for (int o = 16; o > 0; o >>= 1)
        l += __shfl_xor_sync(0xffffffffu, l, o);
    float inv = 1.0f / l;

#pragma unroll
    for (int j = 0; j < 8; j++) {
        int idx = lane * 4 + j * 128;
        float4 p = v[j];
        p.x *= inv; p.y *= inv; p.z *= inv; p.w *= inv;
        *(float4*)&Srow[idx] = p;
    }
}

// ---------------- PV batched GEMM (bf16 hi/lo 3-chain, double-buffered) ----------------
__global__ void __launch_bounds__(256, 2) pv_kernel()
{
    __shared__ uint32_t sAh[2][64 * WST], sAl[2][64 * WST];
    __shared__ uint32_t sBh[2][128 * WST], sBl[2][128 * WST];

    const int tid = threadIdx.x;
    const int warp = tid >> 5, lane = tid & 31;
    const int qrow = lane >> 2, qk = lane & 3;
    const int warpM = warp >> 2;
    const int warpN = warp & 3;
    const int m0 = blockIdx.y << 6;
    const int b  = blockIdx.z >> 4;
    const int h  = blockIdx.z & 15;

    const float* __restrict__ Psrc = g_S + (size_t)(b * H_ + h) * S_ * LC_;

    float acc[2][4][4] = {};

    const int prow = tid >> 2, pw = tid & 3;
    const int pcol = tid >> 1, pwb = (tid & 1) * 4;
    const float* __restrict__ Vsrc = (pcol < 64) ? g_Vr : g_Vi;
    const int vd = pcol & 63;

    float2 pa0, pa1;
    float pv_[8];

    auto load_g = [&](int k0) {
        size_t ga = (size_t)(m0 + prow) * LC_ + k0 + 2 * pw;
        pa0 = *(const float2*)&Psrc[ga];
        pa1 = *(const float2*)&Psrc[ga + 8];
#pragma unroll
        for (int j = 0; j < 8; j++) {
            int k = k0 + 2 * pwb + j;
            pv_[j] = Vsrc[((size_t)(b * LC_ + k)) * F_ + h * HD_ + vd];
        }
    };
    auto store_s = [&](int par) {
        uint32_t wh, wl;
        pack_hilo(pa0.x, pa0.y, wh, wl);
        sAh[par][prow * WST + pw] = wh;  sAl[par][prow * WST + pw] = wl;
        pack_hilo(pa1.x, pa1.y, wh, wl);
        sAh[par][prow * WST + pw + 4] = wh;  sAl[par][prow * WST + pw + 4] = wl;
#pragma unroll
        for (int j = 0; j < 4; j++) {
            pack_hilo(pv_[2 * j], pv_[2 * j + 1], wh, wl);
            sBh[par][pcol * WST + pwb + j] = wh;
            sBl[par][pcol * WST + pwb + j] = wl;
        }
    };

    load_g(0);
    store_s(0);
    __syncthreads();

    const int T = LC_ / 16;
    for (int t = 0; t < T; t++) {
        const bool more = (t + 1 < T);
        if (more) load_g((t + 1) * 16);
        const int par = t & 1;

        uint32_t ah[2][4], al[2][4];
#pragma unroll
        for (int ma = 0; ma < 2; ma++) {
            int mb = warpM * 32 + ma * 16 + qrow;
            ah[ma][0] = sAh[par][(mb)     * WST + qk];
            ah[ma][1] = sAh[par][(mb + 8) * WST + qk];
            ah[ma][2] = sAh[par][(mb)     * WST + qk + 4];
            ah[ma][3] = sAh[par][(mb + 8) * WST + qk + 4];
            al[ma][0] = sAl[par][(mb)     * WST + qk];
            al[ma][1] = sAl[par][(mb + 8) * WST + qk];
            al[ma][2] = sAl[par][(mb)     * WST + qk + 4];
            al[ma][3] = sAl[par][(mb + 8) * WST + qk + 4];
        }
#pragma unroll
        for (int na = 0; na < 4; na++) {
            int nb = warpN * 32 + na * 8 + qrow;
            uint32_t bh[2], bl[2];
            bh[0] = sBh[par][nb * WST + qk];
            bh[1] = sBh[par][nb * WST + qk + 4];
            bl[0] = sBl[par][nb * WST + qk];
            bl[1] = sBl[par][nb * WST + qk + 4];
#pragma unroll
            for (int ma = 0; ma < 2; ma++) {
                mma_bf16(acc[ma][na], ah[ma], bh);
                mma_bf16(acc[ma][na], al[ma], bh);
                mma_bf16(acc[ma][na], ah[ma], bl);
            }
        }

        if (more) {
            store_s(1 - par);
            __syncthreads();
        }
    }

#pragma unroll
    for (int ma = 0; ma < 2; ma++) {
#pragma unroll
        for (int na = 0; na < 4; na++) {
#pragma unroll
            for (int c = 0; c < 4; c++) {
                int row = m0 + warpM * 32 + ma * 16 + qrow + ((c >= 2) ? 8 : 0);
                int col = warpN * 32 + na * 8 + qk * 2 + (c & 1);
                size_t g = ((size_t)(b * S_ + row)) * F_ + h * HD_ + (col & 63);
                if (col < 64) g_Or[g] = acc[ma][na][c];
                else          g_Oi[g] = acc[ma][na][c];
            }
        }
    }
}

// Fallback: bounded zero-fill so graph capture always has nodes.
__global__ void fill_zero_kernel(float* p, long long n)
{
    long long i = (long long)blockIdx.x * blockDim.x + threadIdx.x;
    if (i < n) p[i] = 0.0f;
}

// ---------------- launch ----------------
extern "C" void kernel_launch(void* const* d_in, const int* in_sizes, int n_in,
                              void* d_out, int out_size)
{
    const long long MN = (long long)B_ * S_ * F_;

    const float* x4M[2]  = {0, 0}; int n4M = 0;
    const float* xctx[2] = {0, 0}; int nctx = 0;
    const float* pmask   = 0;
    const float* wF[4]   = {0, 0, 0, 0}; int nwF = 0;
    const float* wC[4]   = {0, 0, 0, 0}; int nwC = 0;
    const float* bias[8] = {0, 0, 0, 0, 0, 0, 0, 0}; int nb = 0;

    for (int i = 0; i < n_in; i++) {
        const float* p = (const float*)d_in[i];
        long long sz = in_sizes[i];
        if (sz == (long long)B_ * S_ * F_)        { if (n4M < 2) x4M[n4M++] = p; }
        else if (sz == (long long)B_ * LC_ * DC_) { if (nctx < 2) xctx[nctx++] = p; }
        else if (sz == (long long)B_ * LC_)       { pmask = p; }
        else if (sz == (long long)F_ * F_)        { if (nwF < 4) wF[nwF++] = p; }
        else if (sz == (long long)DC_ * F_)       { if (nwC < 4) wC[nwC++] = p; }
        else if (sz == (long long)F_)             { if (nb < 8) bias[nb++] = p; }
    }

    const float* x_r = x4M[0],  *x_i = x4M[1];
    const float* ctx_r = xctx[0], *ctx_i = xctx[1];
    const float* Wqr = wF[0], *Wqi = wF[1], *Wor = wF[2], *Woi = wF[3];
    const float* Wkr = wC[0], *Wki = wC[1], *Wvr = wC[2], *Wvi = wC[3];
    const float* bqr = bias[0], *bqi = bias[1];
    const float* bkr = bias[2], *bki = bias[3];
    const float* bvr = bias[4], *bvi = bias[5];
    const float* bor = bias[6], *boi = bias[7];

    int omode = ((long long)out_size >= 2 * MN) ? 2 : 1;

    if (!x_r || !x_i || !ctx_r || !ctx_i || !Wqr || !Wqi || !Wor || !Woi ||
        !Wkr || !Wki || !Wvr || !Wvi) {
        long long n = (omode == 2) ? 2 * MN : MN;
        fill_zero_kernel<<<(unsigned)((n + 255) / 256), 256>>>((float*)d_out, n);
        return;
    }

    cudaFuncSetAttribute(cgemm_kernel<0>, cudaFuncAttributeMaxDynamicSharedMemorySize, CG_SMEM_BYTES);
    cudaFuncSetAttribute(cgemm_kernel<1>, cudaFuncAttributeMaxDynamicSharedMemorySize, CG_SMEM_BYTES);
    cudaFuncSetAttribute(cgemm_kernel<2>, cudaFuncAttributeMaxDynamicSharedMemorySize, CG_SMEM_BYTES);
    cudaFuncSetAttribute(cgemm_kernel<3>, cudaFuncAttributeMaxDynamicSharedMemorySize, CG_SMEM_BYTES);

    dim3 blk(256);

    // projections
    cgemm_kernel<0><<<dim3(F_ / 128, (B_ * S_) / 64), blk, CG_SMEM_BYTES>>>(
        B_ * S_, F_, F_, x_r, x_i, Wqr, Wqi, bqr, bqi, nullptr, 0);
    cgemm_kernel<1><<<dim3(F_ / 128, (B_ * LC_) / 64), blk, CG_SMEM_BYTES>>>(
        B_ * LC_, DC_, F_, ctx_r, ctx_i, Wkr, Wki, bkr, bki, nullptr, 0);
    cgemm_kernel<2><<<dim3(F_ / 128, (B_ * LC_) / 64), blk, CG_SMEM_BYTES>>>(
        B_ * LC_, DC_, F_, ctx_r, ctx_i, Wvr, Wvi, bvr, bvi, nullptr, 0);

    // attention as 3 specialized kernels
    qk_kernel<<<dim3(LC_ / 128, S_ / 64, B_ * H_), blk>>>();
    softmax_kernel<<<(B_ * H_ * S_) / 8, blk>>>(pmask);
    pv_kernel<<<dim3(1, S_ / 64, B_ * H_), blk>>>();

    // output projection
    cgemm_kernel<3><<<dim3(F_ / 128, (B_ * S_) / 64), blk, CG_SMEM_BYTES>>>(
        B_ * S_, F_, F_, nullptr, nullptr, Wor, Woi, bor, boi, (float*)d_out, omode);
}

// round 17
// speedup vs baseline: 1.1943x; 1.0414x over previous
#include <cuda_runtime.h>
#include <cuda_bf16.h>
#include <math.h>
#include <stdint.h>

#define B_   2
#define S_   2048
#define LC_  1024
#define F_   1024
#define DC_  768
#define H_   16
#define HD_  64

// ---------------- scratch (no allocation allowed; zero-initialized) ----------------
__device__ __align__(16) float g_Qr[(size_t)B_ * S_ * F_];
__device__ __align__(16) float g_Qi[(size_t)B_ * S_ * F_];
__device__ __align__(16) float g_Kr[(size_t)B_ * LC_ * F_];
__device__ __align__(16) float g_Ki[(size_t)B_ * LC_ * F_];
__device__ __align__(16) float g_Vr[(size_t)B_ * LC_ * F_];
__device__ __align__(16) float g_Vi[(size_t)B_ * LC_ * F_];
__device__ __align__(16) float g_Or[(size_t)B_ * S_ * F_];
__device__ __align__(16) float g_Oi[(size_t)B_ * S_ * F_];
__device__ __align__(16) float g_S [(size_t)B_ * H_ * S_ * LC_];   // scores -> probs

// ---------------- mma helpers ----------------
__device__ __forceinline__ uint32_t f2tf32(float x) {
    uint32_t r;
    asm("cvt.rna.tf32.f32 %0, %1;" : "=r"(r) : "f"(x));
    return r;
}

__device__ __forceinline__ void mma_tf32(float c[4], const uint32_t a[4], const uint32_t b[2]) {
    asm volatile(
        "mma.sync.aligned.m16n8k8.row.col.f32.tf32.tf32.f32 "
        "{%0,%1,%2,%3}, {%4,%5,%6,%7}, {%8,%9}, {%0,%1,%2,%3};"
        : "+f"(c[0]), "+f"(c[1]), "+f"(c[2]), "+f"(c[3])
        : "r"(a[0]), "r"(a[1]), "r"(a[2]), "r"(a[3]), "r"(b[0]), "r"(b[1]));
}

__device__ __forceinline__ void mma_bf16(float c[4], const uint32_t a[4], const uint32_t b[2]) {
    asm volatile(
        "mma.sync.aligned.m16n8k16.row.col.f32.bf16.bf16.f32 "
        "{%0,%1,%2,%3}, {%4,%5,%6,%7}, {%8,%9}, {%0,%1,%2,%3};"
        : "+f"(c[0]), "+f"(c[1]), "+f"(c[2]), "+f"(c[3])
        : "r"(a[0]), "r"(a[1]), "r"(a[2]), "r"(a[3]), "r"(b[0]), "r"(b[1]));
}

// pack two floats (k even, k odd) into bf16x2 hi-part word + lo-part word
__device__ __forceinline__ void pack_hilo(float x0, float x1, uint32_t& wh, uint32_t& wl) {
    __nv_bfloat16 h0 = __float2bfloat16(x0);
    __nv_bfloat16 h1 = __float2bfloat16(x1);
    __nv_bfloat16 l0 = __float2bfloat16(x0 - __bfloat162float(h0));
    __nv_bfloat16 l1 = __float2bfloat16(x1 - __bfloat162float(h1));
    __nv_bfloat162 hh = __nv_bfloat162(h0, h1);
    __nv_bfloat162 ll = __nv_bfloat162(l0, l1);
    wh = *(uint32_t*)&hh;
    wl = *(uint32_t*)&ll;
}

// ---------------- complex GEMM via tf32 (double-buffered; bni via sign-XOR) ----------------
#define SA_ST 20
#define SB_ST 136
#define CG_A_WORDS (64 * SA_ST)            // 1280
#define CG_B_WORDS (16 * SB_ST)            // 2176
#define CG_BUF_WORDS (2 * CG_A_WORDS + 2 * CG_B_WORDS)   // 6912 (no bni array)
#define CG_SMEM_BYTES (2 * CG_BUF_WORDS * 4)             // 55296

template <int MODE>
__global__ void __launch_bounds__(256, 2) cgemm_kernel(
    int M, int K, int N,
    const float* __restrict__ Ap_r, const float* __restrict__ Ap_i,
    const float* __restrict__ Br, const float* __restrict__ Bi,
    const float* __restrict__ bbr, const float* __restrict__ bbi,
    float* __restrict__ outF, int omode)
{
    const float* __restrict__ Ar = (MODE == 3) ? g_Or : Ap_r;
    const float* __restrict__ Ai = (MODE == 3) ? g_Oi : Ap_i;

    extern __shared__ uint32_t dsm[];

    const int tid = threadIdx.x;
    const int warp = tid >> 5, lane = tid & 31;
    const int qrow = lane >> 2, qk = lane & 3;
    const int warpM = warp >> 2;
    const int warpN = warp & 3;
    const int m0 = blockIdx.y << 6;
    const int n0 = blockIdx.x << 7;

    float accr[2][4][4] = {};
    float acci[2][4][4] = {};

    const int lm = tid >> 4;
    const int lk = tid & 15;
    const int bn = tid & 127;
    const int bkb = tid >> 7;

    float pa_r[4], pa_i[4], pb_r[8], pb_i[8];

    auto load_g = [&](int k0) {
#pragma unroll
        for (int j = 0; j < 4; j++) {
            int m = lm + j * 16;
            size_t g = (size_t)(m0 + m) * K + (k0 + lk);
            pa_r[j] = Ar[g];
            pa_i[j] = Ai[g];
        }
#pragma unroll
        for (int j = 0; j < 8; j++) {
            int kk = bkb + j * 2;
            size_t g = (size_t)(k0 + kk) * N + (n0 + bn);
            pb_r[j] = Br[g];
            pb_i[j] = Bi[g];
        }
    };
    auto store_s = [&](int par) {
        uint32_t* base = dsm + par * CG_BUF_WORDS;
        uint32_t* bAr = base;
        uint32_t* bAi = base + CG_A_WORDS;
        uint32_t* bBr = base + 2 * CG_A_WORDS;
        uint32_t* bBi = bBr + CG_B_WORDS;
#pragma unroll
        for (int j = 0; j < 4; j++) {
            int m = lm + j * 16;
            bAr[m * SA_ST + lk] = f2tf32(pa_r[j]);
            bAi[m * SA_ST + lk] = f2tf32(pa_i[j]);
        }
#pragma unroll
        for (int j = 0; j < 8; j++) {
            int kk = bkb + j * 2;
            bBr[kk * SB_ST + bn] = f2tf32(pb_r[j]);
            bBi[kk * SB_ST + bn] = f2tf32(pb_i[j]);
        }
    };

    load_g(0);
    store_s(0);
    __syncthreads();

    const int T = K / 16;
    for (int t = 0; t < T; t++) {
        const bool more = (t + 1 < T);
        if (more) load_g((t + 1) * 16);

        uint32_t* base = dsm + (t & 1) * CG_BUF_WORDS;
        uint32_t* bAr = base;
        uint32_t* bAi = base + CG_A_WORDS;
        uint32_t* bBr = base + 2 * CG_A_WORDS;
        uint32_t* bBi = bBr + CG_B_WORDS;

#pragma unroll
        for (int kc = 0; kc < 16; kc += 8) {
            uint32_t ar[2][4], ai[2][4];
#pragma unroll
            for (int ma = 0; ma < 2; ma++) {
                int mb = warpM * 32 + ma * 16 + qrow;
                ar[ma][0] = bAr[(mb)     * SA_ST + kc + qk];
                ar[ma][1] = bAr[(mb + 8) * SA_ST + kc + qk];
                ar[ma][2] = bAr[(mb)     * SA_ST + kc + qk + 4];
                ar[ma][3] = bAr[(mb + 8) * SA_ST + kc + qk + 4];
                ai[ma][0] = bAi[(mb)     * SA_ST + kc + qk];
                ai[ma][1] = bAi[(mb + 8) * SA_ST + kc + qk];
                ai[ma][2] = bAi[(mb)     * SA_ST + kc + qk + 4];
                ai[ma][3] = bAi[(mb + 8) * SA_ST + kc + qk + 4];
            }
#pragma unroll
            for (int na = 0; na < 4; na++) {
                int nb = warpN * 32 + na * 8 + qrow;
                uint32_t br_[2], bi_[2], bni_[2];
                br_[0]  = bBr[(kc + qk)     * SB_ST + nb];
                br_[1]  = bBr[(kc + qk + 4) * SB_ST + nb];
                bi_[0]  = bBi[(kc + qk)     * SB_ST + nb];
                bi_[1]  = bBi[(kc + qk + 4) * SB_ST + nb];
                // tf32 negation = sign-bit flip (exact): saves the sBni array
                bni_[0] = bi_[0] ^ 0x80000000u;
                bni_[1] = bi_[1] ^ 0x80000000u;
#pragma unroll
                for (int ma = 0; ma < 2; ma++) {
                    mma_tf32(accr[ma][na], ar[ma], br_);
                    mma_tf32(accr[ma][na], ai[ma], bni_);
                    mma_tf32(acci[ma][na], ar[ma], bi_);
                    mma_tf32(acci[ma][na], ai[ma], br_);
                }
            }
        }

        if (more) {
            store_s((t + 1) & 1);   // opposite buffer: safe vs in-flight mma readers
            __syncthreads();        // ONE barrier per iteration
        }
    }

#pragma unroll
    for (int ma = 0; ma < 2; ma++) {
#pragma unroll
        for (int na = 0; na < 4; na++) {
#pragma unroll
            for (int c = 0; c < 4; c++) {
                int row = m0 + warpM * 32 + ma * 16 + qrow + ((c >= 2) ? 8 : 0);
                int col = n0 + warpN * 32 + na * 8 + qk * 2 + (c & 1);
                float vr = accr[ma][na][c] + (bbr ? bbr[col] : 0.0f);
                float vi = acci[ma][na][c] + (bbi ? bbi[col] : 0.0f);
                size_t idx = (size_t)row * N + col;
                if (MODE == 0)      { g_Qr[idx] = vr; g_Qi[idx] = vi; }
                else if (MODE == 1) { g_Kr[idx] = vr; g_Ki[idx] = vi; }
                else if (MODE == 2) { g_Vr[idx] = vr; g_Vi[idx] = vi; }
                else {
                    if (omode == 2) { outF[2 * idx] = vr; outF[2 * idx + 1] = vi; }
                    else            { outF[idx] = vr; }
                }
            }
        }
    }
}

// ---------------- QK batched GEMM (bf16 hi/lo 3-chain, double-buffered) ----------------
#define WST 12

__global__ void __launch_bounds__(256, 2) qk_kernel()
{
    __shared__ uint32_t sAh[2][64 * WST], sAl[2][64 * WST];
    __shared__ uint32_t sBh[2][128 * WST], sBl[2][128 * WST];

    const int tid = threadIdx.x;
    const int warp = tid >> 5, lane = tid & 31;
    const int qrow = lane >> 2, qk = lane & 3;
    const int warpM = warp >> 2;
    const int warpN = warp & 3;
    const int m0 = blockIdx.y << 6;
    const int n0 = blockIdx.x << 7;
    const int b  = blockIdx.z >> 4;
    const int h  = blockIdx.z & 15;

    float acc[2][4][4] = {};

    const int prow = tid >> 2, pw = tid & 3;
    const int pcol = tid >> 1, pwb = (tid & 1) * 4;

    float2 pa0, pa1;
    float4 pb0, pb1;

    auto load_g = [&](int k0) {
        const float* __restrict__ Qsrc = (k0 < 64) ? g_Qr : g_Qi;
        const float* __restrict__ Ksrc = (k0 < 64) ? g_Kr : g_Ki;
        const int dbase = (k0 & 63);
        size_t ga = ((size_t)(b * S_ + m0 + prow)) * F_ + h * HD_ + dbase + 2 * pw;
        pa0 = *(const float2*)&Qsrc[ga];
        pa1 = *(const float2*)&Qsrc[ga + 8];
        size_t gb = ((size_t)(b * LC_ + n0 + pcol)) * F_ + h * HD_ + dbase + 2 * pwb;
        pb0 = *(const float4*)&Ksrc[gb];
        pb1 = *(const float4*)&Ksrc[gb + 4];
    };
    auto store_s = [&](int par) {
        uint32_t wh, wl;
        pack_hilo(pa0.x, pa0.y, wh, wl);
        sAh[par][prow * WST + pw] = wh;  sAl[par][prow * WST + pw] = wl;
        pack_hilo(pa1.x, pa1.y, wh, wl);
        sAh[par][prow * WST + pw + 4] = wh;  sAl[par][prow * WST + pw + 4] = wl;
        float f[8] = {pb0.x, pb0.y, pb0.z, pb0.w, pb1.x, pb1.y, pb1.z, pb1.w};
#pragma unroll
        for (int j = 0; j < 4; j++) {
            pack_hilo(f[2 * j], f[2 * j + 1], wh, wl);
            sBh[par][pcol * WST + pwb + j] = wh;
            sBl[par][pcol * WST + pwb + j] = wl;
        }
    };

    load_g(0);
    store_s(0);
    __syncthreads();

    for (int t = 0; t < 8; t++) {
        const bool more = (t + 1 < 8);
        if (more) load_g((t + 1) * 16);
        const int par = t & 1;

        uint32_t ah[2][4], al[2][4];
#pragma unroll
        for (int ma = 0; ma < 2; ma++) {
            int mb = warpM * 32 + ma * 16 + qrow;
            ah[ma][0] = sAh[par][(mb)     * WST + qk];
            ah[ma][1] = sAh[par][(mb + 8) * WST + qk];
            ah[ma][2] = sAh[par][(mb)     * WST + qk + 4];
            ah[ma][3] = sAh[par][(mb + 8) * WST + qk + 4];
            al[ma][0] = sAl[par][(mb)     * WST + qk];
            al[ma][1] = sAl[par][(mb + 8) * WST + qk];
            al[ma][2] = sAl[par][(mb)     * WST + qk + 4];
            al[ma][3] = sAl[par][(mb + 8) * WST + qk + 4];
        }
#pragma unroll
        for (int na = 0; na < 4; na++) {
            int nb = warpN * 32 + na * 8 + qrow;
            uint32_t bh[2], bl[2];
            bh[0] = sBh[par][nb * WST + qk];
            bh[1] = sBh[par][nb * WST + qk + 4];
            bl[0] = sBl[par][nb * WST + qk];
            bl[1] = sBl[par][nb * WST + qk + 4];
#pragma unroll
            for (int ma = 0; ma < 2; ma++) {
                mma_bf16(acc[ma][na], ah[ma], bh);
                mma_bf16(acc[ma][na], al[ma], bh);
                mma_bf16(acc[ma][na], ah[ma], bl);
            }
        }

        if (more) {
            store_s(1 - par);
            __syncthreads();
        }
    }

    float* Sdst = g_S + (size_t)(b * H_ + h) * S_ * LC_;
#pragma unroll
    for (int ma = 0; ma < 2; ma++) {
#pragma unroll
        for (int na = 0; na < 4; na++) {
#pragma unroll
            for (int c = 0; c < 4; c++) {
                int row = m0 + warpM * 32 + ma * 16 + qrow + ((c >= 2) ? 8 : 0);
                int col = n0 + warpN * 32 + na * 8 + qk * 2 + (c & 1);
                Sdst[(size_t)row * LC_ + col] = acc[ma][na][c] * 0.125f;
            }
        }
    }
}

// ---------------- softmax: one warp per row, row in registers ----------------
__global__ void __launch_bounds__(256) softmax_kernel(const float* __restrict__ mask)
{
    const int warp = threadIdx.x >> 5, lane = threadIdx.x & 31;
    const long long row = (long long)blockIdx.x * 8 + warp;
    const int b = (int)(row >> 15);
    float* Srow = g_S + row * LC_;

    float4 v[8];
    float mx = -1e30f;
#pragma unroll
    for (int j = 0; j < 8; j++) {
        int idx = lane * 4 + j * 128;
        v[j] = *(const float4*)&Srow[idx];
        if (mask) {
            float4 mk = *(const float4*)&mask[b * LC_ + idx];
            v[j].x += (1.0f - mk.x) * -1e9f;
            v[j].y += (1.0f - mk.y) * -1e9f;
            v[j].z += (1.0f - mk.z) * -1e9f;
            v[j].w += (1.0f - mk.w) * -1e9f;
        }
        mx = fmaxf(mx, fmaxf(fmaxf(v[j].x, v[j].y), fmaxf(v[j].z, v[j].w)));
    }
#pragma unroll
    for (int o = 16; o > 0; o >>= 1)
        mx = fmaxf(mx, __shfl_xor_sync(0xffffffffu, mx, o));

    float l = 0.0f;
#pragma unroll
    for (int j = 0; j < 8; j++) {
        v[j].x = __expf(v[j].x - mx);
        v[j].y = __expf(v[j].y - mx);
        v[j].z = __expf(v[j].z - mx);
        v[j].w = __expf(v[j].w - mx);
        l += v[j].x + v[j].y + v[j].z + v[j].w;
    }
#pragma unroll
    for (int o = 16; o > 0; o >>= 1)
        l += __shfl_xor_sync(0xffffffffu, l, o);
    float inv = 1.0f / l;

#pragma unroll
    for (int j = 0; j < 8; j++) {
        int idx = lane * 4 + j * 128;
        float4 p = v[j];
        p.x *= inv; p.y *= inv; p.z *= inv; p.w *= inv;
        *(float4*)&Srow[idx] = p;
    }
}

// ---------------- PV batched GEMM (bf16 hi/lo 3-chain, double-buffered) ----------------
__global__ void __launch_bounds__(256, 2) pv_kernel()
{
    __shared__ uint32_t sAh[2][64 * WST], sAl[2][64 * WST];
    __shared__ uint32_t sBh[2][128 * WST], sBl[2][128 * WST];

    const int tid = threadIdx.x;
    const int warp = tid >> 5, lane = tid & 31;
    const int qrow = lane >> 2, qk = lane & 3;
    const int warpM = warp >> 2;
    const int warpN = warp & 3;
    const int m0 = blockIdx.y << 6;
    const int b  = blockIdx.z >> 4;
    const int h  = blockIdx.z & 15;

    const float* __restrict__ Psrc = g_S + (size_t)(b * H_ + h) * S_ * LC_;

    float acc[2][4][4] = {};

    const int prow = tid >> 2, pw = tid & 3;
    const int pcol = tid >> 1, pwb = (tid & 1) * 4;
    const float* __restrict__ Vsrc = (pcol < 64) ? g_Vr : g_Vi;
    const int vd = pcol & 63;

    float2 pa0, pa1;
    float pv_[8];

    auto load_g = [&](int k0) {
        size_t ga = (size_t)(m0 + prow) * LC_ + k0 + 2 * pw;
        pa0 = *(const float2*)&Psrc[ga];
        pa1 = *(const float2*)&Psrc[ga + 8];
#pragma unroll
        for (int j = 0; j < 8; j++) {
            int k = k0 + 2 * pwb + j;
            pv_[j] = Vsrc[((size_t)(b * LC_ + k)) * F_ + h * HD_ + vd];
        }
    };
    auto store_s = [&](int par) {
        uint32_t wh, wl;
        pack_hilo(pa0.x, pa0.y, wh, wl);
        sAh[par][prow * WST + pw] = wh;  sAl[par][prow * WST + pw] = wl;
        pack_hilo(pa1.x, pa1.y, wh, wl);
        sAh[par][prow * WST + pw + 4] = wh;  sAl[par][prow * WST + pw + 4] = wl;
#pragma unroll
        for (int j = 0; j < 4; j++) {
            pack_hilo(pv_[2 * j], pv_[2 * j + 1], wh, wl);
            sBh[par][pcol * WST + pwb + j] = wh;
            sBl[par][pcol * WST + pwb + j] = wl;
        }
    };

    load_g(0);
    store_s(0);
    __syncthreads();

    const int T = LC_ / 16;
    for (int t = 0; t < T; t++) {
        const bool more = (t + 1 < T);
        if (more) load_g((t + 1) * 16);
        const int par = t & 1;

        uint32_t ah[2][4], al[2][4];
#pragma unroll
        for (int ma = 0; ma < 2; ma++) {
            int mb = warpM * 32 + ma * 16 + qrow;
            ah[ma][0] = sAh[par][(mb)     * WST + qk];
            ah[ma][1] = sAh[par][(mb + 8) * WST + qk];
            ah[ma][2] = sAh[par][(mb)     * WST + qk + 4];
            ah[ma][3] = sAh[par][(mb + 8) * WST + qk + 4];
            al[ma][0] = sAl[par][(mb)     * WST + qk];
            al[ma][1] = sAl[par][(mb + 8) * WST + qk];
            al[ma][2] = sAl[par][(mb)     * WST + qk + 4];
            al[ma][3] = sAl[par][(mb + 8) * WST + qk + 4];
        }
#pragma unroll
        for (int na = 0; na < 4; na++) {
            int nb = warpN * 32 + na * 8 + qrow;
            uint32_t bh[2], bl[2];
            bh[0] = sBh[par][nb * WST + qk];
            bh[1] = sBh[par][nb * WST + qk + 4];
            bl[0] = sBl[par][nb * WST + qk];
            bl[1] = sBl[par][nb * WST + qk + 4];
#pragma unroll
            for (int ma = 0; ma < 2; ma++) {
                mma_bf16(acc[ma][na], ah[ma], bh);
                mma_bf16(acc[ma][na], al[ma], bh);
                mma_bf16(acc[ma][na], ah[ma], bl);
            }
        }

        if (more) {
            store_s(1 - par);
            __syncthreads();
        }
    }

#pragma unroll
    for (int ma = 0; ma < 2; ma++) {
#pragma unroll
        for (int na = 0; na < 4; na++) {
#pragma unroll
            for (int c = 0; c < 4; c++) {
                int row = m0 + warpM * 32 + ma * 16 + qrow + ((c >= 2) ? 8 : 0);
                int col = warpN * 32 + na * 8 + qk * 2 + (c & 1);
                size_t g = ((size_t)(b * S_ + row)) * F_ + h * HD_ + (col & 63);
                if (col < 64) g_Or[g] = acc[ma][na][c];
                else          g_Oi[g] = acc[ma][na][c];
            }
        }
    }
}

// Fallback: bounded zero-fill so graph capture always has nodes.
__global__ void fill_zero_kernel(float* p, long long n)
{
    long long i = (long long)blockIdx.x * blockDim.x + threadIdx.x;
    if (i < n) p[i] = 0.0f;
}

// ---------------- launch ----------------
extern "C" void kernel_launch(void* const* d_in, const int* in_sizes, int n_in,
                              void* d_out, int out_size)
{
    const long long MN = (long long)B_ * S_ * F_;

    const float* x4M[2]  = {0, 0}; int n4M = 0;
    const float* xctx[2] = {0, 0}; int nctx = 0;
    const float* pmask   = 0;
    const float* wF[4]   = {0, 0, 0, 0}; int nwF = 0;
    const float* wC[4]   = {0, 0, 0, 0}; int nwC = 0;
    const float* bias[8] = {0, 0, 0, 0, 0, 0, 0, 0}; int nb = 0;

    for (int i = 0; i < n_in; i++) {
        const float* p = (const float*)d_in[i];
        long long sz = in_sizes[i];
        if (sz == (long long)B_ * S_ * F_)        { if (n4M < 2) x4M[n4M++] = p; }
        else if (sz == (long long)B_ * LC_ * DC_) { if (nctx < 2) xctx[nctx++] = p; }
        else if (sz == (long long)B_ * LC_)       { pmask = p; }
        else if (sz == (long long)F_ * F_)        { if (nwF < 4) wF[nwF++] = p; }
        else if (sz == (long long)DC_ * F_)       { if (nwC < 4) wC[nwC++] = p; }
        else if (sz == (long long)F_)             { if (nb < 8) bias[nb++] = p; }
    }

    const float* x_r = x4M[0],  *x_i = x4M[1];
    const float* ctx_r = xctx[0], *ctx_i = xctx[1];
    const float* Wqr = wF[0], *Wqi = wF[1], *Wor = wF[2], *Woi = wF[3];
    const float* Wkr = wC[0], *Wki = wC[1], *Wvr = wC[2], *Wvi = wC[3];
    const float* bqr = bias[0], *bqi = bias[1];
    const float* bkr = bias[2], *bki = bias[3];
    const float* bvr = bias[4], *bvi = bias[5];
    const float* bor = bias[6], *boi = bias[7];

    int omode = ((long long)out_size >= 2 * MN) ? 2 : 1;

    if (!x_r || !x_i || !ctx_r || !ctx_i || !Wqr || !Wqi || !Wor || !Woi ||
        !Wkr || !Wki || !Wvr || !Wvi) {
        long long n = (omode == 2) ? 2 * MN : MN;
        fill_zero_kernel<<<(unsigned)((n + 255) / 256), 256>>>((float*)d_out, n);
        return;
    }

    cudaFuncSetAttribute(cgemm_kernel<0>, cudaFuncAttributeMaxDynamicSharedMemorySize, CG_SMEM_BYTES);
    cudaFuncSetAttribute(cgemm_kernel<1>, cudaFuncAttributeMaxDynamicSharedMemorySize, CG_SMEM_BYTES);
    cudaFuncSetAttribute(cgemm_kernel<2>, cudaFuncAttributeMaxDynamicSharedMemorySize, CG_SMEM_BYTES);
    cudaFuncSetAttribute(cgemm_kernel<3>, cudaFuncAttributeMaxDynamicSharedMemorySize, CG_SMEM_BYTES);

    dim3 blk(256);

    // projections
    cgemm_kernel<0><<<dim3(F_ / 128, (B_ * S_) / 64), blk, CG_SMEM_BYTES>>>(
        B_ * S_, F_, F_, x_r, x_i, Wqr, Wqi, bqr, bqi, nullptr, 0);
    cgemm_kernel<1><<<dim3(F_ / 128, (B_ * LC_) / 64), blk, CG_SMEM_BYTES>>>(
        B_ * LC_, DC_, F_, ctx_r, ctx_i, Wkr, Wki, bkr, bki, nullptr, 0);
    cgemm_kernel<2><<<dim3(F_ / 128, (B_ * LC_) / 64), blk, CG_SMEM_BYTES>>>(
        B_ * LC_, DC_, F_, ctx_r, ctx_i, Wvr, Wvi, bvr, bvi, nullptr, 0);

    // attention as 3 specialized kernels
    qk_kernel<<<dim3(LC_ / 128, S_ / 64, B_ * H_), blk>>>();
    softmax_kernel<<<(B_ * H_ * S_) / 8, blk>>>(pmask);
    pv_kernel<<<dim3(1, S_ / 64, B_ * H_), blk>>>();

    // output projection
    cgemm_kernel<3><<<dim3(F_ / 128, (B_ * S_) / 64), blk, CG_SMEM_BYTES>>>(
        B_ * S_, F_, F_, nullptr, nullptr, Wor, Woi, bor, boi, (float*)d_out, omode);
}